// round 5
// baseline (speedup 1.0000x reference)
#include <cuda_runtime.h>

#define NNODES 100000
#define NEDGES 1600000
#define FIN 11
#define HH 128
#define DO 64
#define LNEPS 1e-5f
#define NB ((NNODES + 1023) / 1024)   // 98 scan blocks

typedef unsigned long long u64;

// packed f32x2 helpers (Blackwell fma.rn.f32x2 — 2 fp32 FMAs per instruction)
__device__ __forceinline__ u64 dup2(float x) {
    u64 r; asm("mov.b64 %0, {%1, %1};" : "=l"(r) : "f"(x)); return r;
}
__device__ __forceinline__ void fma2(u64& d, u64 a, u64 b) {
    asm("fma.rn.f32x2 %0, %1, %2, %0;" : "+l"(d) : "l"(a), "l"(b));
}
__device__ __forceinline__ float2 unpk(u64 v) {
    float2 r; asm("mov.b64 {%0, %1}, %2;" : "=f"(r.x), "=f"(r.y) : "l"(v)); return r;
}

// ---------------- scratch ----------------
__device__ int g_cnt[NNODES];          // histogram, then fill cursor
__device__ int g_rowptr[NNODES + 1];
__device__ int g_bsum[128];
__device__ int g_csr[NEDGES];
__device__ __align__(16) float g_h0[(size_t)NNODES * HH];
__device__ __align__(16) float g_xt2[(size_t)NNODES * DO];
__device__ __align__(16) float g_w0t[FIN * HH];   // k-major
__device__ __align__(16) float g_w1t[HH * HH];    // k-major
__device__ __align__(16) float g_w2t[HH * DO];    // k-major

// ---------------- init: zero histogram ----------------
__global__ void k_init() {
    int i = blockIdx.x * blockDim.x + threadIdx.x;
    if (i < NNODES) g_cnt[i] = 0;
}

// ---------------- prep: transpose weights to k-major ----------------
__global__ void k_prep(const float* __restrict__ W0, const float* __restrict__ W1,
                       const float* __restrict__ W2) {
    int i = blockIdx.x * blockDim.x + threadIdx.x;
    if (i < FIN * HH) { int k = i / HH, j = i % HH; g_w0t[i] = W0[j * FIN + k]; }
    if (i < HH * HH)  { int k = i / HH, j = i % HH; g_w1t[i] = W1[j * HH + k]; }
    if (i < HH * DO)  { int k = i / DO, j = i % DO; g_w2t[i] = W2[j * HH + k]; }
}

// ---------------- CSR build ----------------
__global__ void k_hist(const int* __restrict__ ei, int e) {
    int t = blockIdx.x * blockDim.x + threadIdx.x;
    if (t < e) atomicAdd(&g_cnt[ei[e + t]], 1);
}

__global__ void __launch_bounds__(1024) k_scanA(int n) {
    __shared__ int sm[1024];
    int tid = threadIdx.x;
    int i = blockIdx.x * 1024 + tid;
    int v = (i < n) ? g_cnt[i] : 0;
    sm[tid] = v;
    __syncthreads();
#pragma unroll
    for (int off = 1; off < 1024; off <<= 1) {
        int t = (tid >= off) ? sm[tid - off] : 0;
        __syncthreads();
        sm[tid] += t;
        __syncthreads();
    }
    if (i < n) g_rowptr[i] = sm[tid] - v;            // block-local exclusive
    if (tid == 1023) g_bsum[blockIdx.x] = sm[1023];  // block total
}

__global__ void k_scanB() {
    __shared__ int sm[128];
    int tid = threadIdx.x;
    int v = (tid < NB) ? g_bsum[tid] : 0;
    sm[tid] = v;
    __syncthreads();
#pragma unroll
    for (int off = 1; off < 128; off <<= 1) {
        int t = (tid >= off) ? sm[tid - off] : 0;
        __syncthreads();
        sm[tid] += t;
        __syncthreads();
    }
    if (tid < NB) g_bsum[tid] = sm[tid] - v;         // exclusive block offsets
}

__global__ void k_scanC(int n, int e) {
    int i = blockIdx.x * blockDim.x + threadIdx.x;
    if (i < n) {
        g_rowptr[i] += g_bsum[i >> 10];
        g_cnt[i] = 0;                                 // reset -> fill cursor
    }
    if (i == 0) g_rowptr[n] = e;
}

__global__ void k_fill(const int* __restrict__ ei, int e) {
    int t = blockIdx.x * blockDim.x + threadIdx.x;
    if (t >= e) return;
    int tg = ei[e + t];
    int pos = atomicAdd(&g_cnt[tg], 1);
    g_csr[g_rowptr[tg] + pos] = ei[t];
}

// ---------------- fused layer 0: gather(11-dim) + GEMM(11->128)/deg + b0, LN, ReLU ----------------
__global__ void __launch_bounds__(256) k_fused0g(const float* __restrict__ nf,
                                                 const float* __restrict__ b0,
                                                 const float* __restrict__ g0,
                                                 const float* __restrict__ be0, int n) {
    int gw = (blockIdx.x * blockDim.x + threadIdx.x) >> 5;
    int lane = threadIdx.x & 31;
    if (gw >= n) return;
    int rp0 = g_rowptr[gw], rp1 = g_rowptr[gw + 1];

    // gather raw features: lanes 0..10 accumulate one dim each
    float accv = 0.f;
    int j = rp0;
    for (; j + 3 < rp1; j += 4) {
        int s0 = g_csr[j], s1 = g_csr[j + 1], s2 = g_csr[j + 2], s3 = g_csr[j + 3];
        if (lane < FIN) {
            float v0 = nf[(size_t)s0 * FIN + lane];
            float v1 = nf[(size_t)s1 * FIN + lane];
            float v2 = nf[(size_t)s2 * FIN + lane];
            float v3 = nf[(size_t)s3 * FIN + lane];
            accv += v0; accv += v1; accv += v2; accv += v3;
        }
    }
    for (; j < rp1; j++) {
        int s = g_csr[j];
        if (lane < FIN) accv += nf[(size_t)s * FIN + lane];
    }

    float a[FIN];
#pragma unroll
    for (int k = 0; k < FIN; k++) a[k] = __shfl_sync(0xffffffffu, accv, k);

    int d = rp1 - rp0;
    float inv = d > 0 ? 1.f / (float)d : 0.f;
    float bm  = d > 0 ? 1.f : 0.f;

    int j0 = lane * 4;
    u64 acc01 = 0ull, acc23 = 0ull;
#pragma unroll
    for (int k = 0; k < FIN; k++) {
        ulonglong2 w = *(const ulonglong2*)&g_w0t[k * HH + j0];
        u64 ak = dup2(a[k]);
        fma2(acc01, ak, w.x);
        fma2(acc23, ak, w.y);
    }
    float2 p01 = unpk(acc01), p23 = unpk(acc23);
    float4 bv = *(const float4*)&b0[j0];
    float t0 = p01.x * inv + bv.x * bm;
    float t1 = p01.y * inv + bv.y * bm;
    float t2 = p23.x * inv + bv.z * bm;
    float t3 = p23.y * inv + bv.w * bm;

    float s = t0 + t1 + t2 + t3;
    float q = t0 * t0 + t1 * t1 + t2 * t2 + t3 * t3;
#pragma unroll
    for (int off = 16; off; off >>= 1) {
        s += __shfl_xor_sync(0xffffffffu, s, off);
        q += __shfl_xor_sync(0xffffffffu, q, off);
    }
    float mu = s * (1.f / HH);
    float var = q * (1.f / HH) - mu * mu;
    float rs = rsqrtf(var + LNEPS);
    float4 gv = *(const float4*)&g0[j0];
    float4 bev = *(const float4*)&be0[j0];
    float4 h;
    h.x = fmaxf((t0 - mu) * rs * gv.x + bev.x, 0.f);
    h.y = fmaxf((t1 - mu) * rs * gv.y + bev.y, 0.f);
    h.z = fmaxf((t2 - mu) * rs * gv.z + bev.z, 0.f);
    h.w = fmaxf((t3 - mu) * rs * gv.w + bev.w, 0.f);
    *(float4*)&g_h0[(size_t)gw * HH + j0] = h;
}

// ---------------- fused layers 1+2: gather(h0) + GEMM/deg+b1 + LN + ReLU + GEMM2 + b2 ----------------
__global__ void __launch_bounds__(256) k_fused12g(const float* __restrict__ b1,
                                                  const float* __restrict__ g1,
                                                  const float* __restrict__ be1,
                                                  const float* __restrict__ b2, int n) {
    extern __shared__ float sm[];
    float* w1s = sm;                 // 16384 floats
    float* w2s = sm + HH * HH;       // 8192 floats
    int tid = threadIdx.x, lane = tid & 31, warp = tid >> 5;
    float* aw = sm + HH * HH + HH * DO + warp * (4 * HH);  // per-warp staging, 4 rows

    // cooperative weight staging
    {
        const float4* w1g = (const float4*)g_w1t;
        float4* d = (float4*)w1s;
        for (int i = tid; i < HH * HH / 4; i += 256) d[i] = w1g[i];
        const float4* w2g = (const float4*)g_w2t;
        float4* d2 = (float4*)w2s;
        for (int i = tid; i < HH * DO / 4; i += 256) d2[i] = w2g[i];
    }
    __syncthreads();

    int base = (blockIdx.x * 8 + warp) * 4;
    int j0 = lane * 4;

    int nd[4];
    bool val[4];
    int degs[4];
#pragma unroll
    for (int nn = 0; nn < 4; nn++) {
        int node = base + nn;
        val[nn] = node < n;
        nd[nn] = val[nn] ? node : 0;
    }

    // ---- gather h0 rows into staging ----
#pragma unroll
    for (int nn = 0; nn < 4; nn++) {
        if (!val[nn]) { degs[nn] = 0; continue; }     // warp-uniform
        int rp0 = g_rowptr[nd[nn]], rp1 = g_rowptr[nd[nn] + 1];
        degs[nn] = rp1 - rp0;
        float4 acc = make_float4(0.f, 0.f, 0.f, 0.f);
        int j = rp0;
        for (; j + 3 < rp1; j += 4) {
            int s0 = g_csr[j], s1 = g_csr[j + 1], s2 = g_csr[j + 2], s3 = g_csr[j + 3];
            float4 v0 = *(const float4*)&g_h0[(size_t)s0 * HH + j0];
            float4 v1 = *(const float4*)&g_h0[(size_t)s1 * HH + j0];
            float4 v2 = *(const float4*)&g_h0[(size_t)s2 * HH + j0];
            float4 v3 = *(const float4*)&g_h0[(size_t)s3 * HH + j0];
            acc.x += v0.x; acc.y += v0.y; acc.z += v0.z; acc.w += v0.w;
            acc.x += v1.x; acc.y += v1.y; acc.z += v1.z; acc.w += v1.w;
            acc.x += v2.x; acc.y += v2.y; acc.z += v2.z; acc.w += v2.w;
            acc.x += v3.x; acc.y += v3.y; acc.z += v3.z; acc.w += v3.w;
        }
        for (; j < rp1; j++) {
            int s = g_csr[j];
            float4 v = *(const float4*)&g_h0[(size_t)s * HH + j0];
            acc.x += v.x; acc.y += v.y; acc.z += v.z; acc.w += v.w;
        }
        *(float4*)&aw[nn * HH + j0] = acc;
    }
    __syncwarp();

    // ---- GEMM1 from staging (warp-broadcast LDS), packed f32x2 ----
    u64 acc01[4], acc23[4];
#pragma unroll
    for (int nn = 0; nn < 4; nn++) { acc01[nn] = 0ull; acc23[nn] = 0ull; }

#pragma unroll 4
    for (int kt = 0; kt < HH / 4; kt++) {
        ulonglong2 w0 = *(const ulonglong2*)&w1s[(4 * kt + 0) * HH + j0];
        ulonglong2 w1v = *(const ulonglong2*)&w1s[(4 * kt + 1) * HH + j0];
        ulonglong2 w2v = *(const ulonglong2*)&w1s[(4 * kt + 2) * HH + j0];
        ulonglong2 w3v = *(const ulonglong2*)&w1s[(4 * kt + 3) * HH + j0];
#pragma unroll
        for (int nn = 0; nn < 4; nn++) {
            float4 av = *(const float4*)&aw[nn * HH + 4 * kt];   // broadcast
            u64 ax = dup2(av.x), ay = dup2(av.y), az = dup2(av.z), aq = dup2(av.w);
            fma2(acc01[nn], ax, w0.x);  fma2(acc23[nn], ax, w0.y);
            fma2(acc01[nn], ay, w1v.x); fma2(acc23[nn], ay, w1v.y);
            fma2(acc01[nn], az, w2v.x); fma2(acc23[nn], az, w2v.y);
            fma2(acc01[nn], aq, w3v.x); fma2(acc23[nn], aq, w3v.y);
        }
    }
    __syncwarp();   // GEMM1 reads of aw complete before LN overwrites it

    float4 b1v  = *(const float4*)&b1[j0];
    float4 g1v  = *(const float4*)&g1[j0];
    float4 be1v = *(const float4*)&be1[j0];

#pragma unroll
    for (int nn = 0; nn < 4; nn++) {
        if (!val[nn]) continue;            // warp-uniform
        float dd = (float)degs[nn];
        float inv = dd > 0.f ? 1.f / dd : 0.f;
        float bm  = dd > 0.f ? 1.f : 0.f;
        float2 p01 = unpk(acc01[nn]), p23 = unpk(acc23[nn]);
        float t0 = p01.x * inv + b1v.x * bm;
        float t1 = p01.y * inv + b1v.y * bm;
        float t2 = p23.x * inv + b1v.z * bm;
        float t3 = p23.y * inv + b1v.w * bm;
        float s = t0 + t1 + t2 + t3;
        float q = t0 * t0 + t1 * t1 + t2 * t2 + t3 * t3;
#pragma unroll
        for (int off = 16; off; off >>= 1) {
            s += __shfl_xor_sync(0xffffffffu, s, off);
            q += __shfl_xor_sync(0xffffffffu, q, off);
        }
        float mu = s * (1.f / HH);
        float var = q * (1.f / HH) - mu * mu;
        float rs = rsqrtf(var + LNEPS);
        float4 h;
        h.x = fmaxf((t0 - mu) * rs * g1v.x + be1v.x, 0.f);
        h.y = fmaxf((t1 - mu) * rs * g1v.y + be1v.y, 0.f);
        h.z = fmaxf((t2 - mu) * rs * g1v.z + be1v.z, 0.f);
        h.w = fmaxf((t3 - mu) * rs * g1v.w + be1v.w, 0.f);
        *(float4*)&aw[nn * HH + j0] = h;   // reuse staging for h1
    }
    __syncwarp();

    // ---- GEMM2: xt2 = h1 @ W2^T + b2, packed f32x2 ----
    int j2 = lane * 2;
    u64 a2[4];
#pragma unroll
    for (int nn = 0; nn < 4; nn++) a2[nn] = 0ull;

#pragma unroll 4
    for (int kt = 0; kt < HH / 4; kt++) {
        u64 u0 = *(const u64*)&w2s[(4 * kt + 0) * DO + j2];
        u64 u1 = *(const u64*)&w2s[(4 * kt + 1) * DO + j2];
        u64 u2 = *(const u64*)&w2s[(4 * kt + 2) * DO + j2];
        u64 u3 = *(const u64*)&w2s[(4 * kt + 3) * DO + j2];
#pragma unroll
        for (int nn = 0; nn < 4; nn++) {
            float4 hv = *(const float4*)&aw[nn * HH + 4 * kt];   // broadcast
            fma2(a2[nn], dup2(hv.x), u0);
            fma2(a2[nn], dup2(hv.y), u1);
            fma2(a2[nn], dup2(hv.z), u2);
            fma2(a2[nn], dup2(hv.w), u3);
        }
    }
    float2 b2v = *(const float2*)&b2[j2];
#pragma unroll
    for (int nn = 0; nn < 4; nn++) {
        if (!val[nn]) continue;
        float2 p = unpk(a2[nn]);
        *(float2*)&g_xt2[(size_t)nd[nn] * DO + j2] =
            make_float2(p.x + b2v.x, p.y + b2v.y);
    }
}

// ---------------- final: gather(xt2 64-dim)/deg + LN -> out ----------------
__global__ void __launch_bounds__(256) k_gather2_ln(const float* __restrict__ g2,
                                                    const float* __restrict__ be2,
                                                    float* __restrict__ out, int n) {
    int gw = (blockIdx.x * blockDim.x + threadIdx.x) >> 5;
    int lane = threadIdx.x & 31;
    if (gw >= n) return;
    int rp0 = g_rowptr[gw], rp1 = g_rowptr[gw + 1];

    float ax = 0.f, ay = 0.f;
    int j = rp0;
    for (; j + 3 < rp1; j += 4) {
        int s0 = g_csr[j], s1 = g_csr[j + 1], s2 = g_csr[j + 2], s3 = g_csr[j + 3];
        float2 v0 = *(const float2*)&g_xt2[(size_t)s0 * DO + lane * 2];
        float2 v1 = *(const float2*)&g_xt2[(size_t)s1 * DO + lane * 2];
        float2 v2 = *(const float2*)&g_xt2[(size_t)s2 * DO + lane * 2];
        float2 v3 = *(const float2*)&g_xt2[(size_t)s3 * DO + lane * 2];
        ax += v0.x; ay += v0.y;
        ax += v1.x; ay += v1.y;
        ax += v2.x; ay += v2.y;
        ax += v3.x; ay += v3.y;
    }
    for (; j < rp1; j++) {
        int s = g_csr[j];
        float2 v = *(const float2*)&g_xt2[(size_t)s * DO + lane * 2];
        ax += v.x; ay += v.y;
    }

    int d = rp1 - rp0;
    float inv = d > 0 ? 1.f / (float)d : 0.f;
    float v0 = ax * inv, v1 = ay * inv;
    float s = v0 + v1, q = v0 * v0 + v1 * v1;
#pragma unroll
    for (int off = 16; off; off >>= 1) {
        s += __shfl_xor_sync(0xffffffffu, s, off);
        q += __shfl_xor_sync(0xffffffffu, q, off);
    }
    float mu = s * (1.f / DO);
    float var = q * (1.f / DO) - mu * mu;
    float rs = rsqrtf(var + LNEPS);
    int j2 = lane * 2;
    float2 o;
    o.x = (v0 - mu) * rs * g2[j2]     + be2[j2];
    o.y = (v1 - mu) * rs * g2[j2 + 1] + be2[j2 + 1];
    *(float2*)&out[(size_t)gw * DO + j2] = o;
}

// ---------------- launch ----------------
extern "C" void kernel_launch(void* const* d_in, const int* in_sizes, int n_in,
                              void* d_out, int out_size) {
    const float* nf  = (const float*)d_in[0];
    const int*   ei  = (const int*)d_in[1];
    const float* W0  = (const float*)d_in[2];
    const float* b0  = (const float*)d_in[3];
    const float* W1  = (const float*)d_in[4];
    const float* b1  = (const float*)d_in[5];
    const float* W2  = (const float*)d_in[6];
    const float* b2  = (const float*)d_in[7];
    const float* g0  = (const float*)d_in[8];
    const float* be0 = (const float*)d_in[9];
    const float* g1  = (const float*)d_in[10];
    const float* be1 = (const float*)d_in[11];
    const float* g2  = (const float*)d_in[12];
    const float* be2 = (const float*)d_in[13];
    float* out = (float*)d_out;

    int n = in_sizes[0] / FIN;
    int e = in_sizes[1] / 2;

    k_init<<<(n + 255) / 256, 256>>>();
    k_prep<<<(HH * HH + 255) / 256, 256>>>(W0, W1, W2);

    // CSR build
    k_hist<<<(e + 255) / 256, 256>>>(ei, e);
    k_scanA<<<NB, 1024>>>(n);
    k_scanB<<<1, 128>>>();
    k_scanC<<<(n + 255) / 256, 256>>>(n, e);
    k_fill<<<(e + 255) / 256, 256>>>(ei, e);

    // fused layers
    k_fused0g<<<(n + 7) / 8, 256>>>(nf, b0, g0, be0, n);

    const int smem12 = (HH * HH + HH * DO + 8 * 4 * HH) * (int)sizeof(float);  // 114688 B
    cudaFuncSetAttribute(k_fused12g, cudaFuncAttributeMaxDynamicSharedMemorySize, smem12);
    k_fused12g<<<(n + 31) / 32, 256, smem12>>>(b1, g1, be1, b2, n);

    k_gather2_ln<<<(n + 7) / 8, 256>>>(g2, be2, out, n);
}

// round 7
// speedup vs baseline: 1.4382x; 1.4382x over previous
#include <cuda_runtime.h>

#define NNODES 100000
#define NEDGES 1600000
#define FIN 11
#define HH 128
#define DO 64
#define LNEPS 1e-5f
#define NB ((NNODES + 1023) / 1024)   // 98 scan blocks

// ---------------- scratch ----------------
__device__ int g_cnt[NNODES];          // histogram, then fill cursor
__device__ int g_rowptr[NNODES + 1];
__device__ int g_bsum[128];
__device__ int g_csr[NEDGES];
__device__ __align__(16) float g_h0[(size_t)NNODES * HH];
__device__ __align__(16) float g_xt2[(size_t)NNODES * DO];
__device__ __align__(16) float g_w0t[FIN * HH];   // k-major
__device__ __align__(16) float g_w1t[HH * HH];    // k-major
__device__ __align__(16) float g_w2t[HH * DO];    // k-major

// ---------------- setup: zero histogram + transpose weights (merged) ----------------
__global__ void k_setup(const float* __restrict__ W0, const float* __restrict__ W1,
                        const float* __restrict__ W2, int n) {
    int i = blockIdx.x * blockDim.x + threadIdx.x;
    if (i < n) g_cnt[i] = 0;
    if (i < FIN * HH) { int k = i / HH, j = i % HH; g_w0t[i] = W0[j * FIN + k]; }
    if (i < HH * HH)  { int k = i / HH, j = i % HH; g_w1t[i] = W1[j * HH + k]; }
    if (i < HH * DO)  { int k = i / DO, j = i % DO; g_w2t[i] = W2[j * HH + k]; }
}

// ---------------- CSR build ----------------
__global__ void k_hist(const int* __restrict__ ei, int e) {
    int t = blockIdx.x * blockDim.x + threadIdx.x;
    if (t < e) atomicAdd(&g_cnt[ei[e + t]], 1);
}

__global__ void __launch_bounds__(1024) k_scanA(int n) {
    __shared__ int sm[1024];
    int tid = threadIdx.x;
    int i = blockIdx.x * 1024 + tid;
    int v = (i < n) ? g_cnt[i] : 0;
    sm[tid] = v;
    __syncthreads();
#pragma unroll
    for (int off = 1; off < 1024; off <<= 1) {
        int t = (tid >= off) ? sm[tid - off] : 0;
        __syncthreads();
        sm[tid] += t;
        __syncthreads();
    }
    if (i < n) g_rowptr[i] = sm[tid] - v;            // block-local exclusive
    if (tid == 1023) g_bsum[blockIdx.x] = sm[1023];  // block total
}

__global__ void k_scanB() {
    __shared__ int sm[128];
    int tid = threadIdx.x;
    int v = (tid < NB) ? g_bsum[tid] : 0;
    sm[tid] = v;
    __syncthreads();
#pragma unroll
    for (int off = 1; off < 128; off <<= 1) {
        int t = (tid >= off) ? sm[tid - off] : 0;
        __syncthreads();
        sm[tid] += t;
        __syncthreads();
    }
    if (tid < NB) g_bsum[tid] = sm[tid] - v;         // exclusive block offsets
}

__global__ void k_scanC(int n, int e) {
    int i = blockIdx.x * blockDim.x + threadIdx.x;
    if (i < n) {
        g_rowptr[i] += g_bsum[i >> 10];
        g_cnt[i] = 0;                                 // reset -> fill cursor
    }
    if (i == 0) g_rowptr[n] = e;
}

__global__ void k_fill(const int* __restrict__ ei, int e) {
    int t = blockIdx.x * blockDim.x + threadIdx.x;
    if (t >= e) return;
    int tg = ei[e + t];
    int pos = atomicAdd(&g_cnt[tg], 1);
    g_csr[g_rowptr[tg] + pos] = ei[t];
}

// ---------------- fused layer 0: gather(11-dim) + GEMM(11->128)/deg + b0, LN, ReLU ----------------
// gather uses both half-warps: half h handles edges rp0+h, rp0+h+2, ... (dim = lane&15)
__global__ void __launch_bounds__(256) k_fused0g(const float* __restrict__ nf,
                                                 const float* __restrict__ b0,
                                                 const float* __restrict__ g0,
                                                 const float* __restrict__ be0, int n) {
    int gw = (blockIdx.x * blockDim.x + threadIdx.x) >> 5;
    int lane = threadIdx.x & 31;
    if (gw >= n) return;
    int rp0 = g_rowptr[gw], rp1 = g_rowptr[gw + 1];

    int half = lane >> 4;       // 0 or 1
    int dim = lane & 15;
    bool act = dim < FIN;

    float accv = 0.f;
    int j = rp0;
    for (; j + 3 < rp1; j += 4) {                    // 4 edges per iter, 2 per half-warp
        int sa = g_csr[j + half];
        int sb = g_csr[j + 2 + half];
        if (act) {
            accv += nf[(size_t)sa * FIN + dim];
            accv += nf[(size_t)sb * FIN + dim];
        }
    }
    for (; j + 1 < rp1; j += 2) {                    // 2 edges per iter
        int sa = g_csr[j + half];
        if (act) accv += nf[(size_t)sa * FIN + dim];
    }
    if (j < rp1 && half == 0 && act)                 // last odd edge
        accv += nf[(size_t)g_csr[j] * FIN + dim];

    float a[FIN];
#pragma unroll
    for (int k = 0; k < FIN; k++)
        a[k] = __shfl_sync(0xffffffffu, accv, k) + __shfl_sync(0xffffffffu, accv, 16 + k);

    int d = rp1 - rp0;
    float inv = d > 0 ? 1.f / (float)d : 0.f;
    float bm  = d > 0 ? 1.f : 0.f;

    int j0 = lane * 4;
    float a0 = 0.f, a1 = 0.f, a2 = 0.f, a3 = 0.f;
#pragma unroll
    for (int k = 0; k < FIN; k++) {
        float4 w = *(const float4*)&g_w0t[k * HH + j0];
        a0 = fmaf(a[k], w.x, a0);
        a1 = fmaf(a[k], w.y, a1);
        a2 = fmaf(a[k], w.z, a2);
        a3 = fmaf(a[k], w.w, a3);
    }
    float4 bv = *(const float4*)&b0[j0];
    float t0 = a0 * inv + bv.x * bm;
    float t1 = a1 * inv + bv.y * bm;
    float t2 = a2 * inv + bv.z * bm;
    float t3 = a3 * inv + bv.w * bm;

    float s = t0 + t1 + t2 + t3;
    float q = t0 * t0 + t1 * t1 + t2 * t2 + t3 * t3;
#pragma unroll
    for (int off = 16; off; off >>= 1) {
        s += __shfl_xor_sync(0xffffffffu, s, off);
        q += __shfl_xor_sync(0xffffffffu, q, off);
    }
    float mu = s * (1.f / HH);
    float var = q * (1.f / HH) - mu * mu;
    float rs = rsqrtf(var + LNEPS);
    float4 gv = *(const float4*)&g0[j0];
    float4 bev = *(const float4*)&be0[j0];
    float4 h;
    h.x = fmaxf((t0 - mu) * rs * gv.x + bev.x, 0.f);
    h.y = fmaxf((t1 - mu) * rs * gv.y + bev.y, 0.f);
    h.z = fmaxf((t2 - mu) * rs * gv.z + bev.z, 0.f);
    h.w = fmaxf((t3 - mu) * rs * gv.w + bev.w, 0.f);
    *(float4*)&g_h0[(size_t)gw * HH + j0] = h;
}

// ---------------- fused layers 1+2: gather(h0) + GEMM/deg+b1 + LN + ReLU + GEMM2 + b2 ----------------
__global__ void __launch_bounds__(256) k_fused12g(const float* __restrict__ b1,
                                                  const float* __restrict__ g1,
                                                  const float* __restrict__ be1,
                                                  const float* __restrict__ b2, int n) {
    extern __shared__ float sm[];
    float* w1s = sm;                 // 16384 floats
    float* w2s = sm + HH * HH;       // 8192 floats
    int tid = threadIdx.x, lane = tid & 31, warp = tid >> 5;
    float* aw = sm + HH * HH + HH * DO + warp * (4 * HH);  // per-warp staging, 4 rows

    // cooperative weight staging
    {
        const float4* w1g = (const float4*)g_w1t;
        float4* d = (float4*)w1s;
        for (int i = tid; i < HH * HH / 4; i += 256) d[i] = w1g[i];
        const float4* w2g = (const float4*)g_w2t;
        float4* d2 = (float4*)w2s;
        for (int i = tid; i < HH * DO / 4; i += 256) d2[i] = w2g[i];
    }
    __syncthreads();

    int base = (blockIdx.x * 8 + warp) * 4;
    int j0 = lane * 4;

    int nd[4];
    bool val[4];
    int degs[4];
#pragma unroll
    for (int nn = 0; nn < 4; nn++) {
        int node = base + nn;
        val[nn] = node < n;
        nd[nn] = val[nn] ? node : 0;
    }

    // ---- gather h0 rows into staging ----
#pragma unroll
    for (int nn = 0; nn < 4; nn++) {
        if (!val[nn]) { degs[nn] = 0; continue; }     // warp-uniform
        int rp0 = g_rowptr[nd[nn]], rp1 = g_rowptr[nd[nn] + 1];
        degs[nn] = rp1 - rp0;
        float4 acc = make_float4(0.f, 0.f, 0.f, 0.f);
        int j = rp0;
        for (; j + 3 < rp1; j += 4) {
            int s0 = g_csr[j], s1 = g_csr[j + 1], s2 = g_csr[j + 2], s3 = g_csr[j + 3];
            float4 v0 = *(const float4*)&g_h0[(size_t)s0 * HH + j0];
            float4 v1 = *(const float4*)&g_h0[(size_t)s1 * HH + j0];
            float4 v2 = *(const float4*)&g_h0[(size_t)s2 * HH + j0];
            float4 v3 = *(const float4*)&g_h0[(size_t)s3 * HH + j0];
            acc.x += v0.x; acc.y += v0.y; acc.z += v0.z; acc.w += v0.w;
            acc.x += v1.x; acc.y += v1.y; acc.z += v1.z; acc.w += v1.w;
            acc.x += v2.x; acc.y += v2.y; acc.z += v2.z; acc.w += v2.w;
            acc.x += v3.x; acc.y += v3.y; acc.z += v3.z; acc.w += v3.w;
        }
        for (; j < rp1; j++) {
            int s = g_csr[j];
            float4 v = *(const float4*)&g_h0[(size_t)s * HH + j0];
            acc.x += v.x; acc.y += v.y; acc.z += v.z; acc.w += v.w;
        }
        *(float4*)&aw[nn * HH + j0] = acc;
    }
    __syncwarp();

    // ---- GEMM1 from staging (warp-broadcast LDS) ----
    float acc[4][4];
#pragma unroll
    for (int nn = 0; nn < 4; nn++)
#pragma unroll
        for (int i = 0; i < 4; i++) acc[nn][i] = 0.f;

#pragma unroll 4
    for (int kt = 0; kt < HH / 4; kt++) {
        float4 w0 = *(const float4*)&w1s[(4 * kt + 0) * HH + j0];
        float4 w1v = *(const float4*)&w1s[(4 * kt + 1) * HH + j0];
        float4 w2v = *(const float4*)&w1s[(4 * kt + 2) * HH + j0];
        float4 w3v = *(const float4*)&w1s[(4 * kt + 3) * HH + j0];
#pragma unroll
        for (int nn = 0; nn < 4; nn++) {
            float4 av = *(const float4*)&aw[nn * HH + 4 * kt];   // broadcast
            acc[nn][0] = fmaf(av.x, w0.x, fmaf(av.y, w1v.x, fmaf(av.z, w2v.x, fmaf(av.w, w3v.x, acc[nn][0]))));
            acc[nn][1] = fmaf(av.x, w0.y, fmaf(av.y, w1v.y, fmaf(av.z, w2v.y, fmaf(av.w, w3v.y, acc[nn][1]))));
            acc[nn][2] = fmaf(av.x, w0.z, fmaf(av.y, w1v.z, fmaf(av.z, w2v.z, fmaf(av.w, w3v.z, acc[nn][2]))));
            acc[nn][3] = fmaf(av.x, w0.w, fmaf(av.y, w1v.w, fmaf(av.z, w2v.w, fmaf(av.w, w3v.w, acc[nn][3]))));
        }
    }
    __syncwarp();   // GEMM1 reads of aw complete before LN overwrites it

    float4 b1v  = *(const float4*)&b1[j0];
    float4 g1v  = *(const float4*)&g1[j0];
    float4 be1v = *(const float4*)&be1[j0];

#pragma unroll
    for (int nn = 0; nn < 4; nn++) {
        if (!val[nn]) continue;            // warp-uniform
        float dd = (float)degs[nn];
        float inv = dd > 0.f ? 1.f / dd : 0.f;
        float bm  = dd > 0.f ? 1.f : 0.f;
        float t0 = acc[nn][0] * inv + b1v.x * bm;
        float t1 = acc[nn][1] * inv + b1v.y * bm;
        float t2 = acc[nn][2] * inv + b1v.z * bm;
        float t3 = acc[nn][3] * inv + b1v.w * bm;
        float s = t0 + t1 + t2 + t3;
        float q = t0 * t0 + t1 * t1 + t2 * t2 + t3 * t3;
#pragma unroll
        for (int off = 16; off; off >>= 1) {
            s += __shfl_xor_sync(0xffffffffu, s, off);
            q += __shfl_xor_sync(0xffffffffu, q, off);
        }
        float mu = s * (1.f / HH);
        float var = q * (1.f / HH) - mu * mu;
        float rs = rsqrtf(var + LNEPS);
        float4 h;
        h.x = fmaxf((t0 - mu) * rs * g1v.x + be1v.x, 0.f);
        h.y = fmaxf((t1 - mu) * rs * g1v.y + be1v.y, 0.f);
        h.z = fmaxf((t2 - mu) * rs * g1v.z + be1v.z, 0.f);
        h.w = fmaxf((t3 - mu) * rs * g1v.w + be1v.w, 0.f);
        *(float4*)&aw[nn * HH + j0] = h;   // reuse staging for h1
    }
    __syncwarp();

    // ---- GEMM2: xt2 = h1 @ W2^T + b2 (bias unconditional; rides through aggregation) ----
    int j2 = lane * 2;
    float a2[4][2];
#pragma unroll
    for (int nn = 0; nn < 4; nn++) { a2[nn][0] = 0.f; a2[nn][1] = 0.f; }

#pragma unroll 4
    for (int kt = 0; kt < HH / 4; kt++) {
        float2 u0 = *(const float2*)&w2s[(4 * kt + 0) * DO + j2];
        float2 u1 = *(const float2*)&w2s[(4 * kt + 1) * DO + j2];
        float2 u2 = *(const float2*)&w2s[(4 * kt + 2) * DO + j2];
        float2 u3 = *(const float2*)&w2s[(4 * kt + 3) * DO + j2];
#pragma unroll
        for (int nn = 0; nn < 4; nn++) {
            float4 hv = *(const float4*)&aw[nn * HH + 4 * kt];   // broadcast
            a2[nn][0] = fmaf(hv.x, u0.x, fmaf(hv.y, u1.x, fmaf(hv.z, u2.x, fmaf(hv.w, u3.x, a2[nn][0]))));
            a2[nn][1] = fmaf(hv.x, u0.y, fmaf(hv.y, u1.y, fmaf(hv.z, u2.y, fmaf(hv.w, u3.y, a2[nn][1]))));
        }
    }
    float2 b2v = *(const float2*)&b2[j2];
#pragma unroll
    for (int nn = 0; nn < 4; nn++) {
        if (!val[nn]) continue;
        *(float2*)&g_xt2[(size_t)nd[nn] * DO + j2] =
            make_float2(a2[nn][0] + b2v.x, a2[nn][1] + b2v.y);
    }
}

// ---------------- final: gather(xt2 64-dim)/deg + LN -> out ----------------
__global__ void __launch_bounds__(256) k_gather2_ln(const float* __restrict__ g2,
                                                    const float* __restrict__ be2,
                                                    float* __restrict__ out, int n) {
    int gw = (blockIdx.x * blockDim.x + threadIdx.x) >> 5;
    int lane = threadIdx.x & 31;
    if (gw >= n) return;
    int rp0 = g_rowptr[gw], rp1 = g_rowptr[gw + 1];

    float ax = 0.f, ay = 0.f;
    int j = rp0;
    for (; j + 3 < rp1; j += 4) {
        int s0 = g_csr[j], s1 = g_csr[j + 1], s2 = g_csr[j + 2], s3 = g_csr[j + 3];
        float2 v0 = *(const float2*)&g_xt2[(size_t)s0 * DO + lane * 2];
        float2 v1 = *(const float2*)&g_xt2[(size_t)s1 * DO + lane * 2];
        float2 v2 = *(const float2*)&g_xt2[(size_t)s2 * DO + lane * 2];
        float2 v3 = *(const float2*)&g_xt2[(size_t)s3 * DO + lane * 2];
        ax += v0.x; ay += v0.y;
        ax += v1.x; ay += v1.y;
        ax += v2.x; ay += v2.y;
        ax += v3.x; ay += v3.y;
    }
    for (; j < rp1; j++) {
        int s = g_csr[j];
        float2 v = *(const float2*)&g_xt2[(size_t)s * DO + lane * 2];
        ax += v.x; ay += v.y;
    }

    int d = rp1 - rp0;
    float inv = d > 0 ? 1.f / (float)d : 0.f;
    float v0 = ax * inv, v1 = ay * inv;
    float s = v0 + v1, q = v0 * v0 + v1 * v1;
#pragma unroll
    for (int off = 16; off; off >>= 1) {
        s += __shfl_xor_sync(0xffffffffu, s, off);
        q += __shfl_xor_sync(0xffffffffu, q, off);
    }
    float mu = s * (1.f / DO);
    float var = q * (1.f / DO) - mu * mu;
    float rs = rsqrtf(var + LNEPS);
    int j2 = lane * 2;
    float2 o;
    o.x = (v0 - mu) * rs * g2[j2]     + be2[j2];
    o.y = (v1 - mu) * rs * g2[j2 + 1] + be2[j2 + 1];
    *(float2*)&out[(size_t)gw * DO + j2] = o;
}

// ---------------- launch ----------------
extern "C" void kernel_launch(void* const* d_in, const int* in_sizes, int n_in,
                              void* d_out, int out_size) {
    const float* nf  = (const float*)d_in[0];
    const int*   ei  = (const int*)d_in[1];
    const float* W0  = (const float*)d_in[2];
    const float* b0  = (const float*)d_in[3];
    const float* W1  = (const float*)d_in[4];
    const float* b1  = (const float*)d_in[5];
    const float* W2  = (const float*)d_in[6];
    const float* b2  = (const float*)d_in[7];
    const float* g0  = (const float*)d_in[8];
    const float* be0 = (const float*)d_in[9];
    const float* g1  = (const float*)d_in[10];
    const float* be1 = (const float*)d_in[11];
    const float* g2  = (const float*)d_in[12];
    const float* be2 = (const float*)d_in[13];
    float* out = (float*)d_out;

    int n = in_sizes[0] / FIN;
    int e = in_sizes[1] / 2;

    k_setup<<<(n + 255) / 256, 256>>>(W0, W1, W2, n);

    // CSR build
    k_hist<<<(e + 255) / 256, 256>>>(ei, e);
    k_scanA<<<NB, 1024>>>(n);
    k_scanB<<<1, 128>>>();
    k_scanC<<<(n + 255) / 256, 256>>>(n, e);
    k_fill<<<(e + 255) / 256, 256>>>(ei, e);

    // fused layers
    k_fused0g<<<(n + 7) / 8, 256>>>(nf, b0, g0, be0, n);

    const int smem12 = (HH * HH + HH * DO + 8 * 4 * HH) * (int)sizeof(float);  // 114688 B
    cudaFuncSetAttribute(k_fused12g, cudaFuncAttributeMaxDynamicSharedMemorySize, smem12);
    k_fused12g<<<(n + 31) / 32, 256, smem12>>>(b1, g1, be1, b2, n);

    k_gather2_ln<<<(n + 7) / 8, 256>>>(g2, be2, out, n);
}

// round 8
// speedup vs baseline: 1.5943x; 1.1086x over previous
#include <cuda_runtime.h>

#define NNODES 100000
#define NEDGES 1600000
#define FIN 11
#define HH 128
#define DO 64
#define LNEPS 1e-5f
#define NB ((NNODES + 1023) / 1024)   // 98 scan blocks

#define WPB 16      // warps per block in fused12g
#define NPW 8       // nodes per warp in fused12g

// ---------------- scratch ----------------
__device__ int g_cnt[NNODES];          // histogram, then fill cursor
__device__ int g_rowptr[NNODES + 1];
__device__ int g_bsum[128];
__device__ int g_csr[NEDGES];
__device__ __align__(16) float g_h0[(size_t)NNODES * HH];
__device__ __align__(16) float g_xt2[(size_t)NNODES * DO];
__device__ __align__(16) float g_w0t[FIN * HH];   // k-major
__device__ __align__(16) float g_w1t[HH * HH];    // k-major
__device__ __align__(16) float g_w2t[HH * DO];    // k-major

// ---------------- setup: zero histogram + transpose weights (merged) ----------------
__global__ void k_setup(const float* __restrict__ W0, const float* __restrict__ W1,
                        const float* __restrict__ W2, int n) {
    int i = blockIdx.x * blockDim.x + threadIdx.x;
    if (i < n) g_cnt[i] = 0;
    if (i < FIN * HH) { int k = i / HH, j = i % HH; g_w0t[i] = W0[j * FIN + k]; }
    if (i < HH * HH)  { int k = i / HH, j = i % HH; g_w1t[i] = W1[j * HH + k]; }
    if (i < HH * DO)  { int k = i / DO, j = i % DO; g_w2t[i] = W2[j * HH + k]; }
}

// ---------------- CSR build ----------------
__global__ void k_hist(const int* __restrict__ ei, int e) {
    int t = blockIdx.x * blockDim.x + threadIdx.x;
    if (t < e) atomicAdd(&g_cnt[ei[e + t]], 1);
}

__global__ void __launch_bounds__(1024) k_scanA(int n) {
    __shared__ int sm[1024];
    int tid = threadIdx.x;
    int i = blockIdx.x * 1024 + tid;
    int v = (i < n) ? g_cnt[i] : 0;
    sm[tid] = v;
    __syncthreads();
#pragma unroll
    for (int off = 1; off < 1024; off <<= 1) {
        int t = (tid >= off) ? sm[tid - off] : 0;
        __syncthreads();
        sm[tid] += t;
        __syncthreads();
    }
    if (i < n) g_rowptr[i] = sm[tid] - v;            // block-local exclusive
    if (tid == 1023) g_bsum[blockIdx.x] = sm[1023];  // block total
}

__global__ void k_scanB() {
    __shared__ int sm[128];
    int tid = threadIdx.x;
    int v = (tid < NB) ? g_bsum[tid] : 0;
    sm[tid] = v;
    __syncthreads();
#pragma unroll
    for (int off = 1; off < 128; off <<= 1) {
        int t = (tid >= off) ? sm[tid - off] : 0;
        __syncthreads();
        sm[tid] += t;
        __syncthreads();
    }
    if (tid < NB) g_bsum[tid] = sm[tid] - v;         // exclusive block offsets
}

__global__ void k_scanC(int n, int e) {
    int i = blockIdx.x * blockDim.x + threadIdx.x;
    if (i < n) {
        g_rowptr[i] += g_bsum[i >> 10];
        g_cnt[i] = 0;                                 // reset -> fill cursor
    }
    if (i == 0) g_rowptr[n] = e;
}

__global__ void k_fill(const int* __restrict__ ei, int e) {
    int t = blockIdx.x * blockDim.x + threadIdx.x;
    if (t >= e) return;
    int tg = ei[e + t];
    int pos = atomicAdd(&g_cnt[tg], 1);
    g_csr[g_rowptr[tg] + pos] = ei[t];
}

// ---------------- fused layer 0: gather(11-dim) + GEMM(11->128)/deg + b0, LN, ReLU ----------------
__global__ void __launch_bounds__(256) k_fused0g(const float* __restrict__ nf,
                                                 const float* __restrict__ b0,
                                                 const float* __restrict__ g0,
                                                 const float* __restrict__ be0, int n) {
    int gw = (blockIdx.x * blockDim.x + threadIdx.x) >> 5;
    int lane = threadIdx.x & 31;
    if (gw >= n) return;
    int rp0 = g_rowptr[gw], rp1 = g_rowptr[gw + 1];

    int half = lane >> 4;       // 0 or 1
    int dim = lane & 15;
    bool act = dim < FIN;

    float accv = 0.f;
    int j = rp0;
    for (; j + 3 < rp1; j += 4) {                    // 4 edges per iter, 2 per half-warp
        int sa = g_csr[j + half];
        int sb = g_csr[j + 2 + half];
        if (act) {
            accv += nf[(size_t)sa * FIN + dim];
            accv += nf[(size_t)sb * FIN + dim];
        }
    }
    for (; j + 1 < rp1; j += 2) {                    // 2 edges per iter
        int sa = g_csr[j + half];
        if (act) accv += nf[(size_t)sa * FIN + dim];
    }
    if (j < rp1 && half == 0 && act)                 // last odd edge
        accv += nf[(size_t)g_csr[j] * FIN + dim];

    float a[FIN];
#pragma unroll
    for (int k = 0; k < FIN; k++)
        a[k] = __shfl_sync(0xffffffffu, accv, k) + __shfl_sync(0xffffffffu, accv, 16 + k);

    int d = rp1 - rp0;
    float inv = d > 0 ? 1.f / (float)d : 0.f;
    float bm  = d > 0 ? 1.f : 0.f;

    int j0 = lane * 4;
    float a0 = 0.f, a1 = 0.f, a2 = 0.f, a3 = 0.f;
#pragma unroll
    for (int k = 0; k < FIN; k++) {
        float4 w = *(const float4*)&g_w0t[k * HH + j0];
        a0 = fmaf(a[k], w.x, a0);
        a1 = fmaf(a[k], w.y, a1);
        a2 = fmaf(a[k], w.z, a2);
        a3 = fmaf(a[k], w.w, a3);
    }
    float4 bv = *(const float4*)&b0[j0];
    float t0 = a0 * inv + bv.x * bm;
    float t1 = a1 * inv + bv.y * bm;
    float t2 = a2 * inv + bv.z * bm;
    float t3 = a3 * inv + bv.w * bm;

    float s = t0 + t1 + t2 + t3;
    float q = t0 * t0 + t1 * t1 + t2 * t2 + t3 * t3;
#pragma unroll
    for (int off = 16; off; off >>= 1) {
        s += __shfl_xor_sync(0xffffffffu, s, off);
        q += __shfl_xor_sync(0xffffffffu, q, off);
    }
    float mu = s * (1.f / HH);
    float var = q * (1.f / HH) - mu * mu;
    float rs = rsqrtf(var + LNEPS);
    float4 gv = *(const float4*)&g0[j0];
    float4 bev = *(const float4*)&be0[j0];
    float4 h;
    h.x = fmaxf((t0 - mu) * rs * gv.x + bev.x, 0.f);
    h.y = fmaxf((t1 - mu) * rs * gv.y + bev.y, 0.f);
    h.z = fmaxf((t2 - mu) * rs * gv.z + bev.z, 0.f);
    h.w = fmaxf((t3 - mu) * rs * gv.w + bev.w, 0.f);
    *(float4*)&g_h0[(size_t)gw * HH + j0] = h;
}

// ---------------- fused layers 1+2: gather(h0) + GEMM/deg+b1 + LN + ReLU + GEMM2 + b2 ----------------
// 512 threads, 16 warps, 8 nodes per warp — one shared weight copy, FFMA-bound inner loop.
__global__ void __launch_bounds__(512) k_fused12g(const float* __restrict__ b1,
                                                  const float* __restrict__ g1,
                                                  const float* __restrict__ be1,
                                                  const float* __restrict__ b2, int n) {
    extern __shared__ float sm[];
    float* w1s = sm;                 // 16384 floats
    float* w2s = sm + HH * HH;       // 8192 floats
    int tid = threadIdx.x, lane = tid & 31, warp = tid >> 5;
    float* aw = sm + HH * HH + HH * DO + warp * (NPW * HH);  // per-warp staging, NPW rows

    // cooperative weight staging
    {
        const float4* w1g = (const float4*)g_w1t;
        float4* d = (float4*)w1s;
        for (int i = tid; i < HH * HH / 4; i += 512) d[i] = w1g[i];
        const float4* w2g = (const float4*)g_w2t;
        float4* d2 = (float4*)w2s;
        for (int i = tid; i < HH * DO / 4; i += 512) d2[i] = w2g[i];
    }
    __syncthreads();

    int base = (blockIdx.x * WPB + warp) * NPW;
    int j0 = lane * 4;

    int nd[NPW];
    bool val[NPW];
    int degs[NPW];
#pragma unroll
    for (int nn = 0; nn < NPW; nn++) {
        int node = base + nn;
        val[nn] = node < n;
        nd[nn] = val[nn] ? node : 0;
    }

    // ---- gather h0 rows into staging ----
#pragma unroll
    for (int nn = 0; nn < NPW; nn++) {
        if (!val[nn]) { degs[nn] = 0; continue; }     // warp-uniform
        int rp0 = g_rowptr[nd[nn]], rp1 = g_rowptr[nd[nn] + 1];
        degs[nn] = rp1 - rp0;
        float4 acc = make_float4(0.f, 0.f, 0.f, 0.f);
        int j = rp0;
        for (; j + 3 < rp1; j += 4) {
            int s0 = g_csr[j], s1 = g_csr[j + 1], s2 = g_csr[j + 2], s3 = g_csr[j + 3];
            float4 v0 = *(const float4*)&g_h0[(size_t)s0 * HH + j0];
            float4 v1 = *(const float4*)&g_h0[(size_t)s1 * HH + j0];
            float4 v2 = *(const float4*)&g_h0[(size_t)s2 * HH + j0];
            float4 v3 = *(const float4*)&g_h0[(size_t)s3 * HH + j0];
            acc.x += v0.x; acc.y += v0.y; acc.z += v0.z; acc.w += v0.w;
            acc.x += v1.x; acc.y += v1.y; acc.z += v1.z; acc.w += v1.w;
            acc.x += v2.x; acc.y += v2.y; acc.z += v2.z; acc.w += v2.w;
            acc.x += v3.x; acc.y += v3.y; acc.z += v3.z; acc.w += v3.w;
        }
        for (; j < rp1; j++) {
            int s = g_csr[j];
            float4 v = *(const float4*)&g_h0[(size_t)s * HH + j0];
            acc.x += v.x; acc.y += v.y; acc.z += v.z; acc.w += v.w;
        }
        *(float4*)&aw[nn * HH + j0] = acc;
    }
    __syncwarp();

    // ---- GEMM1 from staging (warp-broadcast LDS) ----
    float acc[NPW][4];
#pragma unroll
    for (int nn = 0; nn < NPW; nn++)
#pragma unroll
        for (int i = 0; i < 4; i++) acc[nn][i] = 0.f;

    for (int kt = 0; kt < HH / 4; kt++) {
        float4 w0 = *(const float4*)&w1s[(4 * kt + 0) * HH + j0];
        float4 w1v = *(const float4*)&w1s[(4 * kt + 1) * HH + j0];
        float4 w2v = *(const float4*)&w1s[(4 * kt + 2) * HH + j0];
        float4 w3v = *(const float4*)&w1s[(4 * kt + 3) * HH + j0];
#pragma unroll
        for (int nn = 0; nn < NPW; nn++) {
            float4 av = *(const float4*)&aw[nn * HH + 4 * kt];   // broadcast
            acc[nn][0] = fmaf(av.x, w0.x, fmaf(av.y, w1v.x, fmaf(av.z, w2v.x, fmaf(av.w, w3v.x, acc[nn][0]))));
            acc[nn][1] = fmaf(av.x, w0.y, fmaf(av.y, w1v.y, fmaf(av.z, w2v.y, fmaf(av.w, w3v.y, acc[nn][1]))));
            acc[nn][2] = fmaf(av.x, w0.z, fmaf(av.y, w1v.z, fmaf(av.z, w2v.z, fmaf(av.w, w3v.z, acc[nn][2]))));
            acc[nn][3] = fmaf(av.x, w0.w, fmaf(av.y, w1v.w, fmaf(av.z, w2v.w, fmaf(av.w, w3v.w, acc[nn][3]))));
        }
    }
    __syncwarp();   // GEMM1 reads of aw complete before LN overwrites it

    float4 b1v  = *(const float4*)&b1[j0];
    float4 g1v  = *(const float4*)&g1[j0];
    float4 be1v = *(const float4*)&be1[j0];

#pragma unroll
    for (int nn = 0; nn < NPW; nn++) {
        if (!val[nn]) continue;            // warp-uniform
        float dd = (float)degs[nn];
        float inv = dd > 0.f ? 1.f / dd : 0.f;
        float bm  = dd > 0.f ? 1.f : 0.f;
        float t0 = acc[nn][0] * inv + b1v.x * bm;
        float t1 = acc[nn][1] * inv + b1v.y * bm;
        float t2 = acc[nn][2] * inv + b1v.z * bm;
        float t3 = acc[nn][3] * inv + b1v.w * bm;
        float s = t0 + t1 + t2 + t3;
        float q = t0 * t0 + t1 * t1 + t2 * t2 + t3 * t3;
#pragma unroll
        for (int off = 16; off; off >>= 1) {
            s += __shfl_xor_sync(0xffffffffu, s, off);
            q += __shfl_xor_sync(0xffffffffu, q, off);
        }
        float mu = s * (1.f / HH);
        float var = q * (1.f / HH) - mu * mu;
        float rs = rsqrtf(var + LNEPS);
        float4 h;
        h.x = fmaxf((t0 - mu) * rs * g1v.x + be1v.x, 0.f);
        h.y = fmaxf((t1 - mu) * rs * g1v.y + be1v.y, 0.f);
        h.z = fmaxf((t2 - mu) * rs * g1v.z + be1v.z, 0.f);
        h.w = fmaxf((t3 - mu) * rs * g1v.w + be1v.w, 0.f);
        *(float4*)&aw[nn * HH + j0] = h;   // reuse staging for h1
    }
    __syncwarp();

    // ---- GEMM2: xt2 = h1 @ W2^T + b2 (bias unconditional; rides through aggregation) ----
    int j2 = lane * 2;
    float a2[NPW][2];
#pragma unroll
    for (int nn = 0; nn < NPW; nn++) { a2[nn][0] = 0.f; a2[nn][1] = 0.f; }

    for (int kt = 0; kt < HH / 4; kt++) {
        float2 u0 = *(const float2*)&w2s[(4 * kt + 0) * DO + j2];
        float2 u1 = *(const float2*)&w2s[(4 * kt + 1) * DO + j2];
        float2 u2 = *(const float2*)&w2s[(4 * kt + 2) * DO + j2];
        float2 u3 = *(const float2*)&w2s[(4 * kt + 3) * DO + j2];
#pragma unroll
        for (int nn = 0; nn < NPW; nn++) {
            float4 hv = *(const float4*)&aw[nn * HH + 4 * kt];   // broadcast
            a2[nn][0] = fmaf(hv.x, u0.x, fmaf(hv.y, u1.x, fmaf(hv.z, u2.x, fmaf(hv.w, u3.x, a2[nn][0]))));
            a2[nn][1] = fmaf(hv.x, u0.y, fmaf(hv.y, u1.y, fmaf(hv.z, u2.y, fmaf(hv.w, u3.y, a2[nn][1]))));
        }
    }
    float2 b2v = *(const float2*)&b2[j2];
#pragma unroll
    for (int nn = 0; nn < NPW; nn++) {
        if (!val[nn]) continue;
        *(float2*)&g_xt2[(size_t)nd[nn] * DO + j2] =
            make_float2(a2[nn][0] + b2v.x, a2[nn][1] + b2v.y);
    }
}

// ---------------- final: gather(xt2 64-dim)/deg + LN -> out; half-warp per node ----------------
__global__ void __launch_bounds__(256) k_gather2_ln(const float* __restrict__ g2,
                                                    const float* __restrict__ be2,
                                                    float* __restrict__ out, int n) {
    int gwarp = (blockIdx.x * blockDim.x + threadIdx.x) >> 5;
    int lane = threadIdx.x & 31;
    int half = lane >> 4, l4 = lane & 15;
    int node = gwarp * 2 + half;
    bool ok = node < n;
    int nodec = ok ? node : (n - 1);

    int rp0 = g_rowptr[nodec], rp1 = g_rowptr[nodec + 1];
    int j4 = l4 * 4;                                  // dims j4..j4+3 (covers 64)

    float4 acc = make_float4(0.f, 0.f, 0.f, 0.f);
    int j = rp0;
    for (; j + 1 < rp1; j += 2) {
        int s0 = g_csr[j], s1 = g_csr[j + 1];
        float4 v0 = *(const float4*)&g_xt2[(size_t)s0 * DO + j4];
        float4 v1 = *(const float4*)&g_xt2[(size_t)s1 * DO + j4];
        acc.x += v0.x; acc.y += v0.y; acc.z += v0.z; acc.w += v0.w;
        acc.x += v1.x; acc.y += v1.y; acc.z += v1.z; acc.w += v1.w;
    }
    if (j < rp1) {
        int s0 = g_csr[j];
        float4 v0 = *(const float4*)&g_xt2[(size_t)s0 * DO + j4];
        acc.x += v0.x; acc.y += v0.y; acc.z += v0.z; acc.w += v0.w;
    }

    int d = rp1 - rp0;
    float inv = d > 0 ? 1.f / (float)d : 0.f;
    float t0 = acc.x * inv, t1 = acc.y * inv, t2 = acc.z * inv, t3 = acc.w * inv;

    float s = t0 + t1 + t2 + t3;
    float q = t0 * t0 + t1 * t1 + t2 * t2 + t3 * t3;
#pragma unroll
    for (int off = 8; off; off >>= 1) {               // 16-lane (half-warp) reduction
        s += __shfl_xor_sync(0xffffffffu, s, off);
        q += __shfl_xor_sync(0xffffffffu, q, off);
    }
    float mu = s * (1.f / DO);
    float var = q * (1.f / DO) - mu * mu;
    float rs = rsqrtf(var + LNEPS);
    float4 gv = *(const float4*)&g2[j4];
    float4 bev = *(const float4*)&be2[j4];
    if (ok) {
        float4 o;
        o.x = (t0 - mu) * rs * gv.x + bev.x;
        o.y = (t1 - mu) * rs * gv.y + bev.y;
        o.z = (t2 - mu) * rs * gv.z + bev.z;
        o.w = (t3 - mu) * rs * gv.w + bev.w;
        *(float4*)&out[(size_t)node * DO + j4] = o;
    }
}

// ---------------- launch ----------------
extern "C" void kernel_launch(void* const* d_in, const int* in_sizes, int n_in,
                              void* d_out, int out_size) {
    const float* nf  = (const float*)d_in[0];
    const int*   ei  = (const int*)d_in[1];
    const float* W0  = (const float*)d_in[2];
    const float* b0  = (const float*)d_in[3];
    const float* W1  = (const float*)d_in[4];
    const float* b1  = (const float*)d_in[5];
    const float* W2  = (const float*)d_in[6];
    const float* b2  = (const float*)d_in[7];
    const float* g0  = (const float*)d_in[8];
    const float* be0 = (const float*)d_in[9];
    const float* g1  = (const float*)d_in[10];
    const float* be1 = (const float*)d_in[11];
    const float* g2  = (const float*)d_in[12];
    const float* be2 = (const float*)d_in[13];
    float* out = (float*)d_out;

    int n = in_sizes[0] / FIN;
    int e = in_sizes[1] / 2;

    k_setup<<<(n + 255) / 256, 256>>>(W0, W1, W2, n);

    // CSR build
    k_hist<<<(e + 255) / 256, 256>>>(ei, e);
    k_scanA<<<NB, 1024>>>(n);
    k_scanB<<<1, 128>>>();
    k_scanC<<<(n + 255) / 256, 256>>>(n, e);
    k_fill<<<(e + 255) / 256, 256>>>(ei, e);

    // fused layers
    k_fused0g<<<(n + 7) / 8, 256>>>(nf, b0, g0, be0, n);

    const int smem12 = (HH * HH + HH * DO + WPB * NPW * HH) * (int)sizeof(float);  // 163840 B
    cudaFuncSetAttribute(k_fused12g, cudaFuncAttributeMaxDynamicSharedMemorySize, smem12);
    int nodes_per_block = WPB * NPW;
    k_fused12g<<<(n + nodes_per_block - 1) / nodes_per_block, 512, smem12>>>(b1, g1, be1, b2, n);

    k_gather2_ln<<<(n * 16 + 255) / 256, 256>>>(g2, be2, out, n);
}

// round 9
// speedup vs baseline: 1.6805x; 1.0541x over previous
#include <cuda_runtime.h>
#include <cuda_fp16.h>

#define NNODES 100000
#define NEDGES 1600000
#define FIN 11
#define HH 128
#define DO 64
#define LNEPS 1e-5f
#define NB ((NNODES + 1023) / 1024)   // 98 scan blocks

#define WPB 16      // warps per block in fused12g
#define NPW 8       // nodes per warp in fused12g

// ---------------- scratch ----------------
__device__ int g_cnt[NNODES];          // histogram, then fill cursor
__device__ int g_rowptr[NNODES + 1];
__device__ int g_bsum[128];
__device__ int g_csr[NEDGES];
__device__ __align__(16) __half g_h0h[(size_t)NNODES * HH];   // fp16 staged h0
__device__ __align__(16) __half g_xt2h[(size_t)NNODES * DO];  // fp16 staged xt2
__device__ __align__(16) float g_w0t[FIN * HH];   // k-major
__device__ __align__(16) float g_w1t[HH * HH];    // k-major
__device__ __align__(16) float g_w2t[HH * DO];    // k-major

// ---------------- setup: zero histogram + transpose weights (merged) ----------------
__global__ void k_setup(const float* __restrict__ W0, const float* __restrict__ W1,
                        const float* __restrict__ W2, int n) {
    int i = blockIdx.x * blockDim.x + threadIdx.x;
    if (i < n) g_cnt[i] = 0;
    if (i < FIN * HH) { int k = i / HH, j = i % HH; g_w0t[i] = W0[j * FIN + k]; }
    if (i < HH * HH)  { int k = i / HH, j = i % HH; g_w1t[i] = W1[j * HH + k]; }
    if (i < HH * DO)  { int k = i / DO, j = i % DO; g_w2t[i] = W2[j * HH + k]; }
}

// ---------------- CSR build ----------------
__global__ void k_hist(const int* __restrict__ ei, int e) {
    int t = blockIdx.x * blockDim.x + threadIdx.x;
    if (t < e) atomicAdd(&g_cnt[ei[e + t]], 1);
}

__global__ void __launch_bounds__(1024) k_scanA(int n) {
    __shared__ int sm[1024];
    int tid = threadIdx.x;
    int i = blockIdx.x * 1024 + tid;
    int v = (i < n) ? g_cnt[i] : 0;
    sm[tid] = v;
    __syncthreads();
#pragma unroll
    for (int off = 1; off < 1024; off <<= 1) {
        int t = (tid >= off) ? sm[tid - off] : 0;
        __syncthreads();
        sm[tid] += t;
        __syncthreads();
    }
    if (i < n) g_rowptr[i] = sm[tid] - v;            // block-local exclusive
    if (tid == 1023) g_bsum[blockIdx.x] = sm[1023];  // block total
}

__global__ void k_scanB() {
    __shared__ int sm[128];
    int tid = threadIdx.x;
    int v = (tid < NB) ? g_bsum[tid] : 0;
    sm[tid] = v;
    __syncthreads();
#pragma unroll
    for (int off = 1; off < 128; off <<= 1) {
        int t = (tid >= off) ? sm[tid - off] : 0;
        __syncthreads();
        sm[tid] += t;
        __syncthreads();
    }
    if (tid < NB) g_bsum[tid] = sm[tid] - v;         // exclusive block offsets
}

__global__ void k_scanC(int n, int e) {
    int i = blockIdx.x * blockDim.x + threadIdx.x;
    if (i < n) {
        g_rowptr[i] += g_bsum[i >> 10];
        g_cnt[i] = 0;                                 // reset -> fill cursor
    }
    if (i == 0) g_rowptr[n] = e;
}

__global__ void k_fill(const int* __restrict__ ei, int e) {
    int t = blockIdx.x * blockDim.x + threadIdx.x;
    if (t >= e) return;
    int tg = ei[e + t];
    int pos = atomicAdd(&g_cnt[tg], 1);
    g_csr[g_rowptr[tg] + pos] = ei[t];
}

// ---------------- fused layer 0: gather(11-dim) + GEMM(11->128)/deg + b0, LN, ReLU ----------------
__global__ void __launch_bounds__(256) k_fused0g(const float* __restrict__ nf,
                                                 const float* __restrict__ b0,
                                                 const float* __restrict__ g0,
                                                 const float* __restrict__ be0, int n) {
    int gw = (blockIdx.x * blockDim.x + threadIdx.x) >> 5;
    int lane = threadIdx.x & 31;
    if (gw >= n) return;
    int rp0 = g_rowptr[gw], rp1 = g_rowptr[gw + 1];

    int half = lane >> 4;       // 0 or 1
    int dim = lane & 15;
    bool act = dim < FIN;

    float accv = 0.f;
    int j = rp0;
    for (; j + 3 < rp1; j += 4) {                    // 4 edges per iter, 2 per half-warp
        int sa = g_csr[j + half];
        int sb = g_csr[j + 2 + half];
        if (act) {
            accv += nf[(size_t)sa * FIN + dim];
            accv += nf[(size_t)sb * FIN + dim];
        }
    }
    for (; j + 1 < rp1; j += 2) {                    // 2 edges per iter
        int sa = g_csr[j + half];
        if (act) accv += nf[(size_t)sa * FIN + dim];
    }
    if (j < rp1 && half == 0 && act)                 // last odd edge
        accv += nf[(size_t)g_csr[j] * FIN + dim];

    float a[FIN];
#pragma unroll
    for (int k = 0; k < FIN; k++)
        a[k] = __shfl_sync(0xffffffffu, accv, k) + __shfl_sync(0xffffffffu, accv, 16 + k);

    int d = rp1 - rp0;
    float inv = d > 0 ? 1.f / (float)d : 0.f;
    float bm  = d > 0 ? 1.f : 0.f;

    int j0 = lane * 4;
    float a0 = 0.f, a1 = 0.f, a2 = 0.f, a3 = 0.f;
#pragma unroll
    for (int k = 0; k < FIN; k++) {
        float4 w = *(const float4*)&g_w0t[k * HH + j0];
        a0 = fmaf(a[k], w.x, a0);
        a1 = fmaf(a[k], w.y, a1);
        a2 = fmaf(a[k], w.z, a2);
        a3 = fmaf(a[k], w.w, a3);
    }
    float4 bv = *(const float4*)&b0[j0];
    float t0 = a0 * inv + bv.x * bm;
    float t1 = a1 * inv + bv.y * bm;
    float t2 = a2 * inv + bv.z * bm;
    float t3 = a3 * inv + bv.w * bm;

    float s = t0 + t1 + t2 + t3;
    float q = t0 * t0 + t1 * t1 + t2 * t2 + t3 * t3;
#pragma unroll
    for (int off = 16; off; off >>= 1) {
        s += __shfl_xor_sync(0xffffffffu, s, off);
        q += __shfl_xor_sync(0xffffffffu, q, off);
    }
    float mu = s * (1.f / HH);
    float var = q * (1.f / HH) - mu * mu;
    float rs = rsqrtf(var + LNEPS);
    float4 gv = *(const float4*)&g0[j0];
    float4 bev = *(const float4*)&be0[j0];
    float hx = fmaxf((t0 - mu) * rs * gv.x + bev.x, 0.f);
    float hy = fmaxf((t1 - mu) * rs * gv.y + bev.y, 0.f);
    float hz = fmaxf((t2 - mu) * rs * gv.z + bev.z, 0.f);
    float hw = fmaxf((t3 - mu) * rs * gv.w + bev.w, 0.f);

    // store as fp16 (halves gather1 traffic)
    __half2 p0 = __floats2half2_rn(hx, hy);
    __half2 p1 = __floats2half2_rn(hz, hw);
    uint2 pk;
    pk.x = *(unsigned int*)&p0;
    pk.y = *(unsigned int*)&p1;
    *(uint2*)&g_h0h[(size_t)gw * HH + j0] = pk;
}

// ---------------- fused layers 1+2: gather(h0 fp16) + GEMM/deg+b1 + LN + ReLU + GEMM2 + b2 ----------------
__global__ void __launch_bounds__(512) k_fused12g(const float* __restrict__ b1,
                                                  const float* __restrict__ g1,
                                                  const float* __restrict__ be1,
                                                  const float* __restrict__ b2, int n) {
    extern __shared__ float sm[];
    float* w1s = sm;                 // 16384 floats
    float* w2s = sm + HH * HH;       // 8192 floats
    int tid = threadIdx.x, lane = tid & 31, warp = tid >> 5;
    float* aw = sm + HH * HH + HH * DO + warp * (NPW * HH);  // per-warp staging, NPW rows

    // cooperative weight staging
    {
        const float4* w1g = (const float4*)g_w1t;
        float4* d = (float4*)w1s;
        for (int i = tid; i < HH * HH / 4; i += 512) d[i] = w1g[i];
        const float4* w2g = (const float4*)g_w2t;
        float4* d2 = (float4*)w2s;
        for (int i = tid; i < HH * DO / 4; i += 512) d2[i] = w2g[i];
    }
    __syncthreads();

    int base = (blockIdx.x * WPB + warp) * NPW;
    int j0 = lane * 4;

    int nd[NPW];
    bool val[NPW];
    int degs[NPW];
#pragma unroll
    for (int nn = 0; nn < NPW; nn++) {
        int node = base + nn;
        val[nn] = node < n;
        nd[nn] = val[nn] ? node : 0;
    }

    // ---- gather h0 (fp16) rows into staging, fp32 accumulate ----
#pragma unroll
    for (int nn = 0; nn < NPW; nn++) {
        if (!val[nn]) { degs[nn] = 0; continue; }     // warp-uniform
        int rp0 = g_rowptr[nd[nn]], rp1 = g_rowptr[nd[nn] + 1];
        degs[nn] = rp1 - rp0;
        float4 acc = make_float4(0.f, 0.f, 0.f, 0.f);
        int j = rp0;
        for (; j + 3 < rp1; j += 4) {
            int s0 = g_csr[j], s1 = g_csr[j + 1], s2 = g_csr[j + 2], s3 = g_csr[j + 3];
            uint2 u0 = *(const uint2*)&g_h0h[(size_t)s0 * HH + j0];
            uint2 u1 = *(const uint2*)&g_h0h[(size_t)s1 * HH + j0];
            uint2 u2 = *(const uint2*)&g_h0h[(size_t)s2 * HH + j0];
            uint2 u3 = *(const uint2*)&g_h0h[(size_t)s3 * HH + j0];
            float2 f0a = __half22float2(*(__half2*)&u0.x), f0b = __half22float2(*(__half2*)&u0.y);
            float2 f1a = __half22float2(*(__half2*)&u1.x), f1b = __half22float2(*(__half2*)&u1.y);
            float2 f2a = __half22float2(*(__half2*)&u2.x), f2b = __half22float2(*(__half2*)&u2.y);
            float2 f3a = __half22float2(*(__half2*)&u3.x), f3b = __half22float2(*(__half2*)&u3.y);
            acc.x += f0a.x; acc.y += f0a.y; acc.z += f0b.x; acc.w += f0b.y;
            acc.x += f1a.x; acc.y += f1a.y; acc.z += f1b.x; acc.w += f1b.y;
            acc.x += f2a.x; acc.y += f2a.y; acc.z += f2b.x; acc.w += f2b.y;
            acc.x += f3a.x; acc.y += f3a.y; acc.z += f3b.x; acc.w += f3b.y;
        }
        for (; j < rp1; j++) {
            int s = g_csr[j];
            uint2 u0 = *(const uint2*)&g_h0h[(size_t)s * HH + j0];
            float2 fa = __half22float2(*(__half2*)&u0.x), fb = __half22float2(*(__half2*)&u0.y);
            acc.x += fa.x; acc.y += fa.y; acc.z += fb.x; acc.w += fb.y;
        }
        *(float4*)&aw[nn * HH + j0] = acc;
    }
    __syncwarp();

    // ---- GEMM1 from staging (warp-broadcast LDS) ----
    float acc[NPW][4];
#pragma unroll
    for (int nn = 0; nn < NPW; nn++)
#pragma unroll
        for (int i = 0; i < 4; i++) acc[nn][i] = 0.f;

    for (int kt = 0; kt < HH / 4; kt++) {
        float4 w0 = *(const float4*)&w1s[(4 * kt + 0) * HH + j0];
        float4 w1v = *(const float4*)&w1s[(4 * kt + 1) * HH + j0];
        float4 w2v = *(const float4*)&w1s[(4 * kt + 2) * HH + j0];
        float4 w3v = *(const float4*)&w1s[(4 * kt + 3) * HH + j0];
#pragma unroll
        for (int nn = 0; nn < NPW; nn++) {
            float4 av = *(const float4*)&aw[nn * HH + 4 * kt];   // broadcast
            acc[nn][0] = fmaf(av.x, w0.x, fmaf(av.y, w1v.x, fmaf(av.z, w2v.x, fmaf(av.w, w3v.x, acc[nn][0]))));
            acc[nn][1] = fmaf(av.x, w0.y, fmaf(av.y, w1v.y, fmaf(av.z, w2v.y, fmaf(av.w, w3v.y, acc[nn][1]))));
            acc[nn][2] = fmaf(av.x, w0.z, fmaf(av.y, w1v.z, fmaf(av.z, w2v.z, fmaf(av.w, w3v.z, acc[nn][2]))));
            acc[nn][3] = fmaf(av.x, w0.w, fmaf(av.y, w1v.w, fmaf(av.z, w2v.w, fmaf(av.w, w3v.w, acc[nn][3]))));
        }
    }
    __syncwarp();   // GEMM1 reads of aw complete before LN overwrites it

    float4 b1v  = *(const float4*)&b1[j0];
    float4 g1v  = *(const float4*)&g1[j0];
    float4 be1v = *(const float4*)&be1[j0];

#pragma unroll
    for (int nn = 0; nn < NPW; nn++) {
        if (!val[nn]) continue;            // warp-uniform
        float dd = (float)degs[nn];
        float inv = dd > 0.f ? 1.f / dd : 0.f;
        float bm  = dd > 0.f ? 1.f : 0.f;
        float t0 = acc[nn][0] * inv + b1v.x * bm;
        float t1 = acc[nn][1] * inv + b1v.y * bm;
        float t2 = acc[nn][2] * inv + b1v.z * bm;
        float t3 = acc[nn][3] * inv + b1v.w * bm;
        float s = t0 + t1 + t2 + t3;
        float q = t0 * t0 + t1 * t1 + t2 * t2 + t3 * t3;
#pragma unroll
        for (int off = 16; off; off >>= 1) {
            s += __shfl_xor_sync(0xffffffffu, s, off);
            q += __shfl_xor_sync(0xffffffffu, q, off);
        }
        float mu = s * (1.f / HH);
        float var = q * (1.f / HH) - mu * mu;
        float rs = rsqrtf(var + LNEPS);
        float4 h;
        h.x = fmaxf((t0 - mu) * rs * g1v.x + be1v.x, 0.f);
        h.y = fmaxf((t1 - mu) * rs * g1v.y + be1v.y, 0.f);
        h.z = fmaxf((t2 - mu) * rs * g1v.z + be1v.z, 0.f);
        h.w = fmaxf((t3 - mu) * rs * g1v.w + be1v.w, 0.f);
        *(float4*)&aw[nn * HH + j0] = h;   // reuse staging for h1
    }
    __syncwarp();

    // ---- GEMM2: xt2 = h1 @ W2^T + b2 (bias unconditional; rides through aggregation) ----
    int j2 = lane * 2;
    float a2[NPW][2];
#pragma unroll
    for (int nn = 0; nn < NPW; nn++) { a2[nn][0] = 0.f; a2[nn][1] = 0.f; }

    for (int kt = 0; kt < HH / 4; kt++) {
        float2 u0 = *(const float2*)&w2s[(4 * kt + 0) * DO + j2];
        float2 u1 = *(const float2*)&w2s[(4 * kt + 1) * DO + j2];
        float2 u2 = *(const float2*)&w2s[(4 * kt + 2) * DO + j2];
        float2 u3 = *(const float2*)&w2s[(4 * kt + 3) * DO + j2];
#pragma unroll
        for (int nn = 0; nn < NPW; nn++) {
            float4 hv = *(const float4*)&aw[nn * HH + 4 * kt];   // broadcast
            a2[nn][0] = fmaf(hv.x, u0.x, fmaf(hv.y, u1.x, fmaf(hv.z, u2.x, fmaf(hv.w, u3.x, a2[nn][0]))));
            a2[nn][1] = fmaf(hv.x, u0.y, fmaf(hv.y, u1.y, fmaf(hv.z, u2.y, fmaf(hv.w, u3.y, a2[nn][1]))));
        }
    }
    float2 b2v = *(const float2*)&b2[j2];
#pragma unroll
    for (int nn = 0; nn < NPW; nn++) {
        if (!val[nn]) continue;
        __half2 p = __floats2half2_rn(a2[nn][0] + b2v.x, a2[nn][1] + b2v.y);
        *(unsigned int*)&g_xt2h[(size_t)nd[nn] * DO + j2] = *(unsigned int*)&p;
    }
}

// ---------------- final: gather(xt2 fp16)/deg + LN -> out; half-warp per node ----------------
__global__ void __launch_bounds__(256) k_gather2_ln(const float* __restrict__ g2,
                                                    const float* __restrict__ be2,
                                                    float* __restrict__ out, int n) {
    int gwarp = (blockIdx.x * blockDim.x + threadIdx.x) >> 5;
    int lane = threadIdx.x & 31;
    int half = lane >> 4, l4 = lane & 15;
    int node = gwarp * 2 + half;
    bool ok = node < n;
    int nodec = ok ? node : (n - 1);

    int rp0 = g_rowptr[nodec], rp1 = g_rowptr[nodec + 1];
    int j4 = l4 * 4;                                  // dims j4..j4+3 (covers 64)

    float4 acc = make_float4(0.f, 0.f, 0.f, 0.f);
    int j = rp0;
    for (; j + 1 < rp1; j += 2) {
        int s0 = g_csr[j], s1 = g_csr[j + 1];
        uint2 u0 = *(const uint2*)&g_xt2h[(size_t)s0 * DO + j4];
        uint2 u1 = *(const uint2*)&g_xt2h[(size_t)s1 * DO + j4];
        float2 f0a = __half22float2(*(__half2*)&u0.x), f0b = __half22float2(*(__half2*)&u0.y);
        float2 f1a = __half22float2(*(__half2*)&u1.x), f1b = __half22float2(*(__half2*)&u1.y);
        acc.x += f0a.x; acc.y += f0a.y; acc.z += f0b.x; acc.w += f0b.y;
        acc.x += f1a.x; acc.y += f1a.y; acc.z += f1b.x; acc.w += f1b.y;
    }
    if (j < rp1) {
        int s0 = g_csr[j];
        uint2 u0 = *(const uint2*)&g_xt2h[(size_t)s0 * DO + j4];
        float2 fa = __half22float2(*(__half2*)&u0.x), fb = __half22float2(*(__half2*)&u0.y);
        acc.x += fa.x; acc.y += fa.y; acc.z += fb.x; acc.w += fb.y;
    }

    int d = rp1 - rp0;
    float inv = d > 0 ? 1.f / (float)d : 0.f;
    float t0 = acc.x * inv, t1 = acc.y * inv, t2 = acc.z * inv, t3 = acc.w * inv;

    float s = t0 + t1 + t2 + t3;
    float q = t0 * t0 + t1 * t1 + t2 * t2 + t3 * t3;
#pragma unroll
    for (int off = 8; off; off >>= 1) {               // 16-lane (half-warp) reduction
        s += __shfl_xor_sync(0xffffffffu, s, off);
        q += __shfl_xor_sync(0xffffffffu, q, off);
    }
    float mu = s * (1.f / DO);
    float var = q * (1.f / DO) - mu * mu;
    float rs = rsqrtf(var + LNEPS);
    float4 gv = *(const float4*)&g2[j4];
    float4 bev = *(const float4*)&be2[j4];
    if (ok) {
        float4 o;
        o.x = (t0 - mu) * rs * gv.x + bev.x;
        o.y = (t1 - mu) * rs * gv.y + bev.y;
        o.z = (t2 - mu) * rs * gv.z + bev.z;
        o.w = (t3 - mu) * rs * gv.w + bev.w;
        *(float4*)&out[(size_t)node * DO + j4] = o;
    }
}

// ---------------- launch ----------------
extern "C" void kernel_launch(void* const* d_in, const int* in_sizes, int n_in,
                              void* d_out, int out_size) {
    const float* nf  = (const float*)d_in[0];
    const int*   ei  = (const int*)d_in[1];
    const float* W0  = (const float*)d_in[2];
    const float* b0  = (const float*)d_in[3];
    const float* W1  = (const float*)d_in[4];
    const float* b1  = (const float*)d_in[5];
    const float* W2  = (const float*)d_in[6];
    const float* b2  = (const float*)d_in[7];
    const float* g0  = (const float*)d_in[8];
    const float* be0 = (const float*)d_in[9];
    const float* g1  = (const float*)d_in[10];
    const float* be1 = (const float*)d_in[11];
    const float* g2  = (const float*)d_in[12];
    const float* be2 = (const float*)d_in[13];
    float* out = (float*)d_out;

    int n = in_sizes[0] / FIN;
    int e = in_sizes[1] / 2;

    k_setup<<<(n + 255) / 256, 256>>>(W0, W1, W2, n);

    // CSR build
    k_hist<<<(e + 255) / 256, 256>>>(ei, e);
    k_scanA<<<NB, 1024>>>(n);
    k_scanB<<<1, 128>>>();
    k_scanC<<<(n + 255) / 256, 256>>>(n, e);
    k_fill<<<(e + 255) / 256, 256>>>(ei, e);

    // fused layers
    k_fused0g<<<(n + 7) / 8, 256>>>(nf, b0, g0, be0, n);

    const int smem12 = (HH * HH + HH * DO + WPB * NPW * HH) * (int)sizeof(float);  // 163840 B
    cudaFuncSetAttribute(k_fused12g, cudaFuncAttributeMaxDynamicSharedMemorySize, smem12);
    int nodes_per_block = WPB * NPW;
    k_fused12g<<<(n + nodes_per_block - 1) / nodes_per_block, 512, smem12>>>(b1, g1, be1, b2, n);

    k_gather2_ln<<<(n * 16 + 255) / 256, 256>>>(g2, be2, out, n);
}

// round 11
// speedup vs baseline: 2.5476x; 1.5160x over previous
#include <cuda_runtime.h>
#include <cuda_fp16.h>
#include <cstdint>

#define NNODES 100000
#define NEDGES 1600000
#define FIN 11
#define HH 128
#define DO 64
#define LNEPS 1e-5f
#define NB ((NNODES + 1023) / 1024)   // 98 scan blocks

// ---------------- scratch ----------------
__device__ int g_cnt[NNODES];
__device__ int g_rowptr[NNODES + 1];
__device__ int g_bsum[128];
__device__ int g_csr[NEDGES];
__device__ __align__(16) __half g_h0h[(size_t)NNODES * HH];
__device__ __align__(16) __half g_xt2h[(size_t)NNODES * DO];
__device__ __align__(16) float g_w0t[FIN * HH];          // k-major fp32
__device__ __align__(16) __half g_w1h[HH * HH];          // fp16 row-major [out][in]
__device__ __align__(16) __half g_w2h[DO * HH];          // fp16 row-major [out][in]

// ---------------- mma helpers (baseline PTX — legal on compute_103) ----------------
__device__ __forceinline__ uint32_t smem_u32(const void* p) {
    uint32_t a;
    asm("{ .reg .u64 t; cvta.to.shared.u64 t, %1; cvt.u32.u64 %0, t; }" : "=r"(a) : "l"(p));
    return a;
}
__device__ __forceinline__ void ldsm4(uint32_t* r, uint32_t addr) {
    asm volatile("ldmatrix.sync.aligned.m8n8.x4.shared.b16 {%0,%1,%2,%3}, [%4];"
        : "=r"(r[0]), "=r"(r[1]), "=r"(r[2]), "=r"(r[3]) : "r"(addr));
}
__device__ __forceinline__ void ldsm2(uint32_t* r, uint32_t addr) {
    asm volatile("ldmatrix.sync.aligned.m8n8.x2.shared.b16 {%0,%1}, [%2];"
        : "=r"(r[0]), "=r"(r[1]) : "r"(addr));
}
__device__ __forceinline__ void mma16816(float* c, const uint32_t* a, const uint32_t* b) {
    asm volatile(
        "mma.sync.aligned.m16n8k16.row.col.f32.f16.f16.f32 "
        "{%0,%1,%2,%3}, {%4,%5,%6,%7}, {%8,%9}, {%0,%1,%2,%3};"
        : "+f"(c[0]), "+f"(c[1]), "+f"(c[2]), "+f"(c[3])
        : "r"(a[0]), "r"(a[1]), "r"(a[2]), "r"(a[3]), "r"(b[0]), "r"(b[1]));
}

// ---------------- setup: zero histogram + weight prep ----------------
__global__ void k_setup(const float* __restrict__ W0, const float* __restrict__ W1,
                        const float* __restrict__ W2, int n) {
    int i = blockIdx.x * blockDim.x + threadIdx.x;
    if (i < n) g_cnt[i] = 0;
    if (i < FIN * HH) { int k = i / HH, j = i % HH; g_w0t[i] = W0[j * FIN + k]; }
    if (i < HH * HH) g_w1h[i] = __float2half(W1[i]);
    if (i < DO * HH) g_w2h[i] = __float2half(W2[i]);
}

// ---------------- CSR build ----------------
__global__ void k_hist(const int* __restrict__ ei, int e) {
    int t = blockIdx.x * blockDim.x + threadIdx.x;
    if (t < e) atomicAdd(&g_cnt[ei[e + t]], 1);
}

__global__ void __launch_bounds__(1024) k_scanA(int n) {
    __shared__ int sm[1024];
    int tid = threadIdx.x;
    int i = blockIdx.x * 1024 + tid;
    int v = (i < n) ? g_cnt[i] : 0;
    sm[tid] = v;
    __syncthreads();
#pragma unroll
    for (int off = 1; off < 1024; off <<= 1) {
        int t = (tid >= off) ? sm[tid - off] : 0;
        __syncthreads();
        sm[tid] += t;
        __syncthreads();
    }
    if (i < n) g_rowptr[i] = sm[tid] - v;
    if (tid == 1023) g_bsum[blockIdx.x] = sm[1023];
}

__global__ void k_scanB() {
    __shared__ int sm[128];
    int tid = threadIdx.x;
    int v = (tid < NB) ? g_bsum[tid] : 0;
    sm[tid] = v;
    __syncthreads();
#pragma unroll
    for (int off = 1; off < 128; off <<= 1) {
        int t = (tid >= off) ? sm[tid - off] : 0;
        __syncthreads();
        sm[tid] += t;
        __syncthreads();
    }
    if (tid < NB) g_bsum[tid] = sm[tid] - v;
}

__global__ void k_scanC(int n, int e) {
    int i = blockIdx.x * blockDim.x + threadIdx.x;
    if (i < n) {
        g_rowptr[i] += g_bsum[i >> 10];
        g_cnt[i] = 0;
    }
    if (i == 0) g_rowptr[n] = e;
}

__global__ void k_fill(const int* __restrict__ ei, int e) {
    int t = blockIdx.x * blockDim.x + threadIdx.x;
    if (t >= e) return;
    int tg = ei[e + t];
    int pos = atomicAdd(&g_cnt[tg], 1);
    g_csr[g_rowptr[tg] + pos] = ei[t];
}

// ---------------- fused layer 0 (unchanged from R9) ----------------
__global__ void __launch_bounds__(256) k_fused0g(const float* __restrict__ nf,
                                                 const float* __restrict__ b0,
                                                 const float* __restrict__ g0,
                                                 const float* __restrict__ be0, int n) {
    int gw = (blockIdx.x * blockDim.x + threadIdx.x) >> 5;
    int lane = threadIdx.x & 31;
    if (gw >= n) return;
    int rp0 = g_rowptr[gw], rp1 = g_rowptr[gw + 1];

    int half = lane >> 4;
    int dim = lane & 15;
    bool act = dim < FIN;

    float accv = 0.f;
    int j = rp0;
    for (; j + 3 < rp1; j += 4) {
        int sa = g_csr[j + half];
        int sb = g_csr[j + 2 + half];
        if (act) {
            accv += nf[(size_t)sa * FIN + dim];
            accv += nf[(size_t)sb * FIN + dim];
        }
    }
    for (; j + 1 < rp1; j += 2) {
        int sa = g_csr[j + half];
        if (act) accv += nf[(size_t)sa * FIN + dim];
    }
    if (j < rp1 && half == 0 && act)
        accv += nf[(size_t)g_csr[j] * FIN + dim];

    float a[FIN];
#pragma unroll
    for (int k = 0; k < FIN; k++)
        a[k] = __shfl_sync(0xffffffffu, accv, k) + __shfl_sync(0xffffffffu, accv, 16 + k);

    int d = rp1 - rp0;
    float inv = d > 0 ? 1.f / (float)d : 0.f;
    float bm  = d > 0 ? 1.f : 0.f;

    int j0 = lane * 4;
    float a0 = 0.f, a1 = 0.f, a2 = 0.f, a3 = 0.f;
#pragma unroll
    for (int k = 0; k < FIN; k++) {
        float4 w = *(const float4*)&g_w0t[k * HH + j0];
        a0 = fmaf(a[k], w.x, a0);
        a1 = fmaf(a[k], w.y, a1);
        a2 = fmaf(a[k], w.z, a2);
        a3 = fmaf(a[k], w.w, a3);
    }
    float4 bv = *(const float4*)&b0[j0];
    float t0 = a0 * inv + bv.x * bm;
    float t1 = a1 * inv + bv.y * bm;
    float t2 = a2 * inv + bv.z * bm;
    float t3 = a3 * inv + bv.w * bm;

    float s = t0 + t1 + t2 + t3;
    float q = t0 * t0 + t1 * t1 + t2 * t2 + t3 * t3;
#pragma unroll
    for (int off = 16; off; off >>= 1) {
        s += __shfl_xor_sync(0xffffffffu, s, off);
        q += __shfl_xor_sync(0xffffffffu, q, off);
    }
    float mu = s * (1.f / HH);
    float var = q * (1.f / HH) - mu * mu;
    float rs = rsqrtf(var + LNEPS);
    float4 gv = *(const float4*)&g0[j0];
    float4 bev = *(const float4*)&be0[j0];
    float hx = fmaxf((t0 - mu) * rs * gv.x + bev.x, 0.f);
    float hy = fmaxf((t1 - mu) * rs * gv.y + bev.y, 0.f);
    float hz = fmaxf((t2 - mu) * rs * gv.z + bev.z, 0.f);
    float hw = fmaxf((t3 - mu) * rs * gv.w + bev.w, 0.f);

    __half2 p0 = __floats2half2_rn(hx, hy);
    __half2 p1 = __floats2half2_rn(hz, hw);
    uint2 pk;
    pk.x = *(unsigned int*)&p0;
    pk.y = *(unsigned int*)&p1;
    *(uint2*)&g_h0h[(size_t)gw * HH + j0] = pk;
}

// ---------------- fused layers 1+2 via mma.sync (HMMA f16, f32 accum) ----------------
// 256 threads = 8 warps; warp owns 16 nodes (M=16); 128 nodes/block.
// SMEM (bytes): params 0..2304 | W1 [128][136]h | W2 [64][136]h | per-warp A staging [16][136]h
#define LDH   136                       // padded row stride in halves (272 B)
#define S_B1  0
#define S_G1  512
#define S_BE1 1024
#define S_B2  1536
#define S_DEG 1792
#define S_W1  2304
#define S_W2  (S_W1 + HH * LDH * 2)     // 2304 + 34816 = 37120
#define S_SA  (S_W2 + DO * LDH * 2)     // 37120 + 17408 = 54528
#define S_TOT (S_SA + 8 * 16 * LDH * 2) // 54528 + 34816 = 89344

__global__ void __launch_bounds__(256, 2) k_fused12m(const float* __restrict__ b1,
                                                     const float* __restrict__ g1,
                                                     const float* __restrict__ be1,
                                                     const float* __restrict__ b2, int n) {
    extern __shared__ char smem[];
    uint32_t sb = smem_u32(smem);
    int tid = threadIdx.x, lane = tid & 31, wid = tid >> 5;
    int base = blockIdx.x * 128;

    // stage weights (row-major, padded rows) + params
    {
        for (int i = tid; i < HH * (HH / 8); i += 256) {           // 2048 uint4
            int r = i >> 4, c = i & 15;
            *(uint4*)(smem + S_W1 + r * (LDH * 2) + c * 16) = ((const uint4*)g_w1h)[i];
        }
        for (int i = tid; i < DO * (HH / 8); i += 256) {           // 1024 uint4
            int r = i >> 4, c = i & 15;
            *(uint4*)(smem + S_W2 + r * (LDH * 2) + c * 16) = ((const uint4*)g_w2h)[i];
        }
        if (tid < 128) {
            ((float*)(smem + S_B1))[tid] = b1[tid];
            ((float*)(smem + S_G1))[tid] = g1[tid];
            ((float*)(smem + S_BE1))[tid] = be1[tid];
            if (tid < 64) ((float*)(smem + S_B2))[tid] = b2[tid];
        }
    }

    char* swA = smem + S_SA + wid * (16 * LDH * 2);
    uint32_t swAu = sb + S_SA + wid * (16 * LDH * 2);
    int* degs = (int*)(smem + S_DEG);

    // ---- gather: warp w fills A[16][128] fp16 (mean-aggregated h0) ----
    for (int r = 0; r < 16; r++) {
        int node = base + wid * 16 + r;
        uint2 pk = make_uint2(0u, 0u);
        int d = 0;
        if (node < n) {
            int rp0 = g_rowptr[node], rp1 = g_rowptr[node + 1];
            d = rp1 - rp0;
            float4 acc = make_float4(0.f, 0.f, 0.f, 0.f);
            int j = rp0;
            for (; j + 1 < rp1; j += 2) {
                int s0 = g_csr[j], s1 = g_csr[j + 1];
                uint2 u0 = *(const uint2*)&g_h0h[(size_t)s0 * HH + lane * 4];
                uint2 u1 = *(const uint2*)&g_h0h[(size_t)s1 * HH + lane * 4];
                float2 f0a = __half22float2(*(__half2*)&u0.x), f0b = __half22float2(*(__half2*)&u0.y);
                float2 f1a = __half22float2(*(__half2*)&u1.x), f1b = __half22float2(*(__half2*)&u1.y);
                acc.x += f0a.x; acc.y += f0a.y; acc.z += f0b.x; acc.w += f0b.y;
                acc.x += f1a.x; acc.y += f1a.y; acc.z += f1b.x; acc.w += f1b.y;
            }
            if (j < rp1) {
                int s0 = g_csr[j];
                uint2 u0 = *(const uint2*)&g_h0h[(size_t)s0 * HH + lane * 4];
                float2 fa = __half22float2(*(__half2*)&u0.x), fb = __half22float2(*(__half2*)&u0.y);
                acc.x += fa.x; acc.y += fa.y; acc.z += fb.x; acc.w += fb.y;
            }
            float inv = d > 0 ? 1.f / (float)d : 0.f;
            __half2 h0 = __floats2half2_rn(acc.x * inv, acc.y * inv);
            __half2 h1 = __floats2half2_rn(acc.z * inv, acc.w * inv);
            pk.x = *(unsigned int*)&h0;
            pk.y = *(unsigned int*)&h1;
        }
        if (lane == 0) degs[wid * 16 + r] = d;
        *(uint2*)(swA + r * (LDH * 2) + lane * 8) = pk;
    }
    __syncthreads();   // weights + own staging visible

    const float* b1s = (const float*)(smem + S_B1);
    const float* g1s = (const float*)(smem + S_G1);
    const float* be1s = (const float*)(smem + S_BE1);
    const float* b2s = (const float*)(smem + S_B2);

    // A-frag address: row = lane&15, col halves = kk*16 + (lane>>4)*8
    uint32_t aAddr = swAu + (lane & 15) * (LDH * 2) + (lane >> 4) * 16;
    // B-frag address: row n = j*8 + (lane&7), col halves = kk*16 + ((lane>>3)&1)*8
    uint32_t bRow = (lane & 7) * (LDH * 2) + ((lane >> 3) & 1) * 16;

    // ---- GEMM1: D[16][128] = A @ W1^T ----
    float acc[16][4];
#pragma unroll
    for (int j = 0; j < 16; j++)
#pragma unroll
        for (int i = 0; i < 4; i++) acc[j][i] = 0.f;

#pragma unroll
    for (int kk = 0; kk < 8; kk++) {
        uint32_t a[4];
        ldsm4(a, aAddr + kk * 32);
#pragma unroll
        for (int j = 0; j < 16; j++) {
            uint32_t b[2];
            ldsm2(b, sb + S_W1 + j * 8 * (LDH * 2) + bRow + kk * 32);
            mma16816(acc[j], a, b);
        }
    }

    // ---- epilogue 1: +b1 (deg-gated), LN over 128, ReLU -> fp16 back into A ----
    {
        int r0 = lane >> 2;                       // local rows r0, r0+8
        float bm0 = degs[wid * 16 + r0] > 0 ? 1.f : 0.f;
        float bm1 = degs[wid * 16 + r0 + 8] > 0 ? 1.f : 0.f;
        float s0 = 0.f, q0 = 0.f, s1 = 0.f, q1 = 0.f;
#pragma unroll
        for (int j = 0; j < 16; j++) {
            int col0 = j * 8 + 2 * (lane & 3);
            float bb0 = b1s[col0], bb1 = b1s[col0 + 1];
            acc[j][0] += bb0 * bm0; acc[j][1] += bb1 * bm0;
            acc[j][2] += bb0 * bm1; acc[j][3] += bb1 * bm1;
            s0 += acc[j][0] + acc[j][1];
            q0 += acc[j][0] * acc[j][0] + acc[j][1] * acc[j][1];
            s1 += acc[j][2] + acc[j][3];
            q1 += acc[j][2] * acc[j][2] + acc[j][3] * acc[j][3];
        }
#pragma unroll
        for (int off = 1; off <= 2; off <<= 1) {  // reduce across quad (same row)
            s0 += __shfl_xor_sync(0xffffffffu, s0, off);
            q0 += __shfl_xor_sync(0xffffffffu, q0, off);
            s1 += __shfl_xor_sync(0xffffffffu, s1, off);
            q1 += __shfl_xor_sync(0xffffffffu, q1, off);
        }
        float mu0 = s0 * (1.f / HH), mu1 = s1 * (1.f / HH);
        float rs0 = rsqrtf(q0 * (1.f / HH) - mu0 * mu0 + LNEPS);
        float rs1 = rsqrtf(q1 * (1.f / HH) - mu1 * mu1 + LNEPS);
#pragma unroll
        for (int j = 0; j < 16; j++) {
            int col0 = j * 8 + 2 * (lane & 3);
            float gg0 = g1s[col0], gg1 = g1s[col0 + 1];
            float bb0 = be1s[col0], bb1 = be1s[col0 + 1];
            float h00 = fmaxf((acc[j][0] - mu0) * rs0 * gg0 + bb0, 0.f);
            float h01 = fmaxf((acc[j][1] - mu0) * rs0 * gg1 + bb1, 0.f);
            float h10 = fmaxf((acc[j][2] - mu1) * rs1 * gg0 + bb0, 0.f);
            float h11 = fmaxf((acc[j][3] - mu1) * rs1 * gg1 + bb1, 0.f);
            *(__half2*)(swA + r0 * (LDH * 2) + col0 * 2) = __floats2half2_rn(h00, h01);
            *(__half2*)(swA + (r0 + 8) * (LDH * 2) + col0 * 2) = __floats2half2_rn(h10, h11);
        }
    }
    __syncwarp();   // staging stores visible to ldmatrix (cross-lane)

    // ---- GEMM2: D2[16][64] = h1 @ W2^T ----
    float acc2[8][4];
#pragma unroll
    for (int j = 0; j < 8; j++)
#pragma unroll
        for (int i = 0; i < 4; i++) acc2[j][i] = 0.f;

#pragma unroll
    for (int kk = 0; kk < 8; kk++) {
        uint32_t a[4];
        ldsm4(a, aAddr + kk * 32);
#pragma unroll
        for (int j = 0; j < 8; j++) {
            uint32_t b[2];
            ldsm2(b, sb + S_W2 + j * 8 * (LDH * 2) + bRow + kk * 32);
            mma16816(acc2[j], a, b);
        }
    }

    // ---- epilogue 2: +b2 -> fp16 -> global ----
    {
        int r0 = lane >> 2;
        int n0 = base + wid * 16 + r0;
        int n1 = n0 + 8;
#pragma unroll
        for (int j = 0; j < 8; j++) {
            int col0 = j * 8 + 2 * (lane & 3);
            float bb0 = b2s[col0], bb1 = b2s[col0 + 1];
            if (n0 < n)
                *(__half2*)&g_xt2h[(size_t)n0 * DO + col0] =
                    __floats2half2_rn(acc2[j][0] + bb0, acc2[j][1] + bb1);
            if (n1 < n)
                *(__half2*)&g_xt2h[(size_t)n1 * DO + col0] =
                    __floats2half2_rn(acc2[j][2] + bb0, acc2[j][3] + bb1);
        }
    }
}

// ---------------- final: gather(xt2 fp16)/deg + LN -> out; half-warp per node ----------------
__global__ void __launch_bounds__(256) k_gather2_ln(const float* __restrict__ g2,
                                                    const float* __restrict__ be2,
                                                    float* __restrict__ out, int n) {
    int gwarp = (blockIdx.x * blockDim.x + threadIdx.x) >> 5;
    int lane = threadIdx.x & 31;
    int half = lane >> 4, l4 = lane & 15;
    int node = gwarp * 2 + half;
    bool ok = node < n;
    int nodec = ok ? node : (n - 1);

    int rp0 = g_rowptr[nodec], rp1 = g_rowptr[nodec + 1];
    int j4 = l4 * 4;

    float4 acc = make_float4(0.f, 0.f, 0.f, 0.f);
    int j = rp0;
    for (; j + 1 < rp1; j += 2) {
        int s0 = g_csr[j], s1 = g_csr[j + 1];
        uint2 u0 = *(const uint2*)&g_xt2h[(size_t)s0 * DO + j4];
        uint2 u1 = *(const uint2*)&g_xt2h[(size_t)s1 * DO + j4];
        float2 f0a = __half22float2(*(__half2*)&u0.x), f0b = __half22float2(*(__half2*)&u0.y);
        float2 f1a = __half22float2(*(__half2*)&u1.x), f1b = __half22float2(*(__half2*)&u1.y);
        acc.x += f0a.x; acc.y += f0a.y; acc.z += f0b.x; acc.w += f0b.y;
        acc.x += f1a.x; acc.y += f1a.y; acc.z += f1b.x; acc.w += f1b.y;
    }
    if (j < rp1) {
        int s0 = g_csr[j];
        uint2 u0 = *(const uint2*)&g_xt2h[(size_t)s0 * DO + j4];
        float2 fa = __half22float2(*(__half2*)&u0.x), fb = __half22float2(*(__half2*)&u0.y);
        acc.x += fa.x; acc.y += fa.y; acc.z += fb.x; acc.w += fb.y;
    }

    int d = rp1 - rp0;
    float inv = d > 0 ? 1.f / (float)d : 0.f;
    float t0 = acc.x * inv, t1 = acc.y * inv, t2 = acc.z * inv, t3 = acc.w * inv;

    float s = t0 + t1 + t2 + t3;
    float q = t0 * t0 + t1 * t1 + t2 * t2 + t3 * t3;
#pragma unroll
    for (int off = 8; off; off >>= 1) {
        s += __shfl_xor_sync(0xffffffffu, s, off);
        q += __shfl_xor_sync(0xffffffffu, q, off);
    }
    float mu = s * (1.f / DO);
    float var = q * (1.f / DO) - mu * mu;
    float rs = rsqrtf(var + LNEPS);
    float4 gv = *(const float4*)&g2[j4];
    float4 bev = *(const float4*)&be2[j4];
    if (ok) {
        float4 o;
        o.x = (t0 - mu) * rs * gv.x + bev.x;
        o.y = (t1 - mu) * rs * gv.y + bev.y;
        o.z = (t2 - mu) * rs * gv.z + bev.z;
        o.w = (t3 - mu) * rs * gv.w + bev.w;
        *(float4*)&out[(size_t)node * DO + j4] = o;
    }
}

// ---------------- launch ----------------
extern "C" void kernel_launch(void* const* d_in, const int* in_sizes, int n_in,
                              void* d_out, int out_size) {
    const float* nf  = (const float*)d_in[0];
    const int*   ei  = (const int*)d_in[1];
    const float* W0  = (const float*)d_in[2];
    const float* b0  = (const float*)d_in[3];
    const float* W1  = (const float*)d_in[4];
    const float* b1  = (const float*)d_in[5];
    const float* W2  = (const float*)d_in[6];
    const float* b2  = (const float*)d_in[7];
    const float* g0  = (const float*)d_in[8];
    const float* be0 = (const float*)d_in[9];
    const float* g1  = (const float*)d_in[10];
    const float* be1 = (const float*)d_in[11];
    const float* g2  = (const float*)d_in[12];
    const float* be2 = (const float*)d_in[13];
    float* out = (float*)d_out;

    int n = in_sizes[0] / FIN;
    int e = in_sizes[1] / 2;

    k_setup<<<(n + 255) / 256, 256>>>(W0, W1, W2, n);

    // CSR build
    k_hist<<<(e + 255) / 256, 256>>>(ei, e);
    k_scanA<<<NB, 1024>>>(n);
    k_scanB<<<1, 128>>>();
    k_scanC<<<(n + 255) / 256, 256>>>(n, e);
    k_fill<<<(e + 255) / 256, 256>>>(ei, e);

    // fused layers
    k_fused0g<<<(n + 7) / 8, 256>>>(nf, b0, g0, be0, n);

    cudaFuncSetAttribute(k_fused12m, cudaFuncAttributeMaxDynamicSharedMemorySize, S_TOT);
    k_fused12m<<<(n + 127) / 128, 256, S_TOT>>>(b1, g1, be1, b2, n);

    k_gather2_ln<<<(n * 16 + 255) / 256, 256>>>(g2, be2, out, n);
}